// round 13
// baseline (speedup 1.0000x reference)
#include <cuda_runtime.h>
#include <cuda_bf16.h>
#include <cstdint>

#define Bc 8
#define Nn 8192
#define Kk 6
#define Dd 256
#define Ll 5
#define BN 65536
#define QLD 768

// ===================== device scratch =====================
__device__ float g_h  [(size_t)BN * Dd];
__device__ float g_qkv[(size_t)BN * 3 * Dd];
__device__ float g_va [(size_t)BN * Dd];
__device__ float g_vb [(size_t)BN * Dd];
__device__ float g_ka [(size_t)BN * Dd];
__device__ float g_kb [(size_t)BN * Dd];
__device__ float g_scal[BN];
__device__ float g_kvm [Bc * Dd * Dd];
__device__ float g_ksum[Bc * Dd];

// CSR (transposed adjacency)
__device__ int g_deg[BN];
__device__ int g_cursor[BN];
__device__ int g_rowstart[BN + 1];
__device__ int g_csr_src[BN * Kk];
__device__ int g_part[64];
__device__ int g_partoff[64];

__device__ __align__(128) __nv_bfloat16 g_hn_hi[(size_t)BN * Dd], g_hn_lo[(size_t)BN * Dd];
__device__ __align__(128) __nv_bfloat16 g_a_hi [(size_t)BN * Dd], g_a_lo [(size_t)BN * Dd];
__device__ __align__(128) __nv_bfloat16 g_vbh  [(size_t)BN * Dd], g_vbl  [(size_t)BN * Dd];
__device__ __align__(128) __nv_bfloat16 g_kT_hi[(size_t)Bc * Dd * Nn], g_kT_lo[(size_t)Bc * Dd * Nn];
__device__ __align__(128) __nv_bfloat16 g_vT_hi[(size_t)Bc * Dd * Nn], g_vT_lo[(size_t)Bc * Dd * Nn];
__device__ __align__(128) __nv_bfloat16 g_kvT_hi[Bc * Dd * Dd], g_kvT_lo[Bc * Dd * Dd];
__device__ __align__(128) __nv_bfloat16 g_wgq_hi[Ll * 3 * Dd * Dd], g_wgq_lo[Ll * 3 * Dd * Dd];
__device__ __align__(128) __nv_bfloat16 g_waq_hi[Ll * 3 * Dd * Dd], g_waq_lo[Ll * 3 * Dd * Dd];
__device__ __align__(128) __nv_bfloat16 g_wgo_hi[Ll * Dd * Dd],     g_wgo_lo[Ll * Dd * Dd];
__device__ __align__(128) __nv_bfloat16 g_wao_hi[Ll * Dd * Dd],     g_wao_lo[Ll * Dd * Dd];

// ===================== PTX helpers (base PTX, sm_103-legal) ============
__device__ __forceinline__ uint32_t smem_to_u32(const void* p) {
    uint32_t a;
    asm("{ .reg .u64 t; cvta.to.shared.u64 t, %1; cvt.u32.u64 %0, t; }" : "=r"(a) : "l"(p));
    return a;
}
#define LDSM_X4(r0, r1, r2, r3, addr) \
    asm volatile("ldmatrix.sync.aligned.m8n8.x4.shared.b16 {%0,%1,%2,%3}, [%4];" \
        : "=r"(r0), "=r"(r1), "=r"(r2), "=r"(r3) : "r"(addr))
#define MMA_BF16(d, a, b) \
    asm volatile("mma.sync.aligned.m16n8k16.row.col.f32.bf16.bf16.f32 " \
        "{%0,%1,%2,%3}, {%4,%5,%6,%7}, {%8,%9}, {%0,%1,%2,%3};" \
        : "+f"((d)[0]), "+f"((d)[1]), "+f"((d)[2]), "+f"((d)[3]) \
        : "r"((a)[0]), "r"((a)[1]), "r"((a)[2]), "r"((a)[3]), "r"((b)[0]), "r"((b)[1]))
#define CP_ASYNC16(s, g) \
    asm volatile("cp.async.cg.shared.global [%0], [%1], 16;" :: "r"(s), "l"(g))
#define CP_COMMIT() asm volatile("cp.async.commit_group;" ::: "memory")
#define CP_WAIT0()  asm volatile("cp.async.wait_group 0;" ::: "memory")

__device__ __forceinline__ void split2(float v, __nv_bfloat16& hi, __nv_bfloat16& lo) {
    hi = __float2bfloat16(v);
    lo = __float2bfloat16(v - __bfloat162float(hi));
}

// ===================== tensor-core GEMM: CTA tile 128x256, 16 warps ==========
// warp grid 4(m) x 4(n), warp tile 32x64; split-bf16 3-term, acc-major order.
// B fragments consumed in two half-batches per kk to cap registers (<128).
// smem per stage: Ah(10240) Al(10240) Bh(20480) Bl(20480) = 61440; 2 stages.
// flags: 1 store fp32, 2 add fp32, 4 atomicAdd fp32, 8 store bf16-split (n<bf16Limit)
#define STG 61440
#define SM_GEMM 122880

__global__ __launch_bounds__(512, 1) void tc_gemm(
    const __nv_bfloat16* __restrict__ Ah, const __nv_bfloat16* __restrict__ Al, int lda, int aBatchRows,
    const __nv_bfloat16* __restrict__ Bh, const __nv_bfloat16* __restrict__ Bl, int ldb, int bBatchRows,
    int nsplit, int kChunks,
    float* __restrict__ C, int ldc, int cBatchRows,
    const float* __restrict__ bias, const float* __restrict__ rowscale,
    __nv_bfloat16* __restrict__ Oh, __nv_bfloat16* __restrict__ Ol, int ldo,
    int reluLimit, int bf16Limit, int flags)
{
    extern __shared__ char dsm[];
    uint32_t sb = smem_to_u32(dsm);
    int t = threadIdx.x, wid = t >> 5, lane = t & 31;
    int batch = blockIdx.z / nsplit, ks = blockIdx.z % nsplit;
    int m0 = blockIdx.x * 128, n0 = blockIdx.y * 256;
    int kBase = ks * kChunks * 32;
    long aRow0 = (long)batch * aBatchRows + m0;
    long bRow0 = (long)batch * bBatchRows + n0;
    int wm = (wid & 3) * 32;     // warp m offset
    int wn = (wid >> 2) * 64;    // warp n offset

    float acc[2][8][4];
#pragma unroll
    for (int i = 0; i < 2; i++)
#pragma unroll
        for (int j = 0; j < 8; j++)
#pragma unroll
            for (int r = 0; r < 4; r++) acc[i][j][r] = 0.f;

    int arow_ld = t >> 2, aseg = t & 3;        // A: 128 rows x 4 16B segs
    int brow_ld = t >> 1, bseg = (t & 1) * 2;  // B: 256 rows x 2 double-segs

#define LOAD_STAGE(c, st) do { \
        int kb = kBase + (c) * 32; \
        uint32_t sbase = sb + (st) * STG; \
        { \
            long ao = (aRow0 + arow_ld) * (long)lda + kb + aseg * 8; \
            uint32_t so = (uint32_t)arow_ld * 80 + aseg * 16; \
            CP_ASYNC16(sbase + so,         (const char*)(Ah + ao)); \
            CP_ASYNC16(sbase + 10240 + so, (const char*)(Al + ao)); \
        } \
        { \
            long bo = (bRow0 + brow_ld) * (long)ldb + kb + bseg * 8; \
            uint32_t so = (uint32_t)brow_ld * 80 + bseg * 16; \
            CP_ASYNC16(sbase + 20480 + so,      (const char*)(Bh + bo)); \
            CP_ASYNC16(sbase + 20480 + so + 16, (const char*)(Bh + bo + 8)); \
            CP_ASYNC16(sbase + 40960 + so,      (const char*)(Bl + bo)); \
            CP_ASYNC16(sbase + 40960 + so + 16, (const char*)(Bl + bo + 8)); \
        } \
        CP_COMMIT(); \
    } while (0)

    LOAD_STAGE(0, 0);

    for (int c = 0; c < kChunks; ++c) {
        int st = c & 1;
        CP_WAIT0();
        __syncthreads();
        if (c + 1 < kChunks) LOAD_STAGE(c + 1, (c + 1) & 1);

        uint32_t uAh = sb + st * STG, uAl = uAh + 10240;
        uint32_t uBh = uAh + 20480,   uBl = uAh + 40960;
#pragma unroll
        for (int kk = 0; kk < 2; ++kk) {
            int kbb = kk * 16;
            uint32_t ah[2][4], al[2][4];
            int arow = (lane & 7) + ((lane >> 3) & 1) * 8;
            int acol = kbb + (lane >> 4) * 8;
#pragma unroll
            for (int mt = 0; mt < 2; ++mt) {
                uint32_t off = (uint32_t)(wm + mt * 16 + arow) * 80 + acol * 2;
                LDSM_X4(ah[mt][0], ah[mt][1], ah[mt][2], ah[mt][3], uAh + off);
                LDSM_X4(al[mt][0], al[mt][1], al[mt][2], al[mt][3], uAl + off);
            }
            int brow = (lane & 7) + ((lane >> 4) & 1) * 8;
            int bcol = kbb + ((lane >> 3) & 1) * 8;
#pragma unroll
            for (int half = 0; half < 2; ++half) {
                uint32_t bh[4][2], bl[4][2];
#pragma unroll
                for (int p = 0; p < 2; ++p) {
                    int pg = half * 2 + p;
                    uint32_t off = (uint32_t)(wn + pg * 16 + brow) * 80 + bcol * 2;
                    LDSM_X4(bh[2 * p][0], bh[2 * p][1], bh[2 * p + 1][0], bh[2 * p + 1][1], uBh + off);
                    LDSM_X4(bl[2 * p][0], bl[2 * p][1], bl[2 * p + 1][0], bl[2 * p + 1][1], uBl + off);
                }
#pragma unroll
                for (int mt = 0; mt < 2; ++mt)
#pragma unroll
                    for (int nt = 0; nt < 4; ++nt) {
                        int idx = half * 4 + nt;
                        MMA_BF16(acc[mt][idx], ah[mt], bh[nt]);
                        MMA_BF16(acc[mt][idx], ah[mt], bl[nt]);
                        MMA_BF16(acc[mt][idx], al[mt], bh[nt]);
                    }
            }
        }
    }

    // epilogue: warp covers rows [wm, wm+32), cols [wn, wn+64)
#pragma unroll
    for (int mt = 0; mt < 2; ++mt) {
        int r0g = m0 + wm + mt * 16 + (lane >> 2);
        long row0 = (long)batch * cBatchRows + r0g;
        long row1 = row0 + 8;
        float rs0 = rowscale ? rowscale[row0] : 1.f;
        float rs1 = rowscale ? rowscale[row1] : 1.f;
#pragma unroll
        for (int nt = 0; nt < 8; ++nt) {
            int c0 = n0 + wn + nt * 8 + (lane & 3) * 2;
#pragma unroll
            for (int half = 0; half < 2; ++half) {
                long row = half ? row1 : row0;
                float rs = half ? rs1 : rs0;
#pragma unroll
                for (int cc = 0; cc < 2; ++cc) {
                    float v = acc[mt][nt][half * 2 + cc] * rs;
                    int n = c0 + cc;
                    if (n < reluLimit) v = fmaxf(v, 0.f) + 1e-6f;
                    if (bias) v += bias[n];
                    if (flags & 1) C[row * ldc + n] = v;
                    if (flags & 2) C[row * ldc + n] += v;
                    if (flags & 4) atomicAdd(&C[row * ldc + n], v);
                    if ((flags & 8) && n < bf16Limit) {
                        __nv_bfloat16 hi, lo;
                        split2(v, hi, lo);
                        Oh[row * ldo + n] = hi;
                        Ol[row * ldo + n] = lo;
                    }
                }
            }
        }
    }
}

// ===================== SIMT kernels =====================
__device__ __forceinline__ float warp_sum(float v) {
#pragma unroll
    for (int o = 16; o > 0; o >>= 1) v += __shfl_xor_sync(0xffffffffu, v, o);
    return v;
}

__global__ void embed_kernel(const float* __restrict__ x, const float* __restrict__ w,
                             const float* __restrict__ b) {
    int row = blockIdx.x, t = threadIdx.x;
    float x0 = x[row * 3], x1 = x[row * 3 + 1], x2 = x[row * 3 + 2];
    g_h[(size_t)row * Dd + t] = b[t] + x0 * w[t] + x1 * w[Dd + t] + x2 * w[2 * Dd + t];
}

__global__ void ln_kernel(const float* __restrict__ g, const float* __restrict__ b) {
    int row = blockIdx.x, t = threadIdx.x;
    float x = g_h[(size_t)row * Dd + t];
    float s = warp_sum(x), s2 = warp_sum(x * x);
    __shared__ float sh1[8], sh2[8];
    int w = t >> 5, l = t & 31;
    if (l == 0) { sh1[w] = s; sh2[w] = s2; }
    __syncthreads();
    if (t == 0) {
        float a = 0.f, c = 0.f;
#pragma unroll
        for (int i = 0; i < 8; i++) { a += sh1[i]; c += sh2[i]; }
        sh1[0] = a; sh2[0] = c;
    }
    __syncthreads();
    float m = sh1[0] * (1.0f / Dd);
    float var = fmaxf(sh2[0] * (1.0f / Dd) - m * m, 0.0f);
    float inv = rsqrtf(var + 1e-5f);
    float y = (x - m) * inv * g[t] + b[t];
    __nv_bfloat16 hi, lo;
    split2(y, hi, lo);
    g_hn_hi[(size_t)row * Dd + t] = hi;
    g_hn_lo[(size_t)row * Dd + t] = lo;
}

__global__ void tsplit(const float* __restrict__ in, int ldi, long inB,
                       __nv_bfloat16* __restrict__ oh, __nv_bfloat16* __restrict__ ol,
                       int ldo, long oB) {
    int z = blockIdx.z;
    in += (long)z * inB; oh += (long)z * oB; ol += (long)z * oB;
    __shared__ float tb[32][33];
    int c0 = blockIdx.x * 32, r0 = blockIdx.y * 32;
    int tx = threadIdx.x & 31, ty = threadIdx.x >> 5;
#pragma unroll
    for (int i = 0; i < 4; ++i) {
        int r = ty + i * 8;
        tb[r][tx] = in[(long)(r0 + r) * ldi + c0 + tx];
    }
    __syncthreads();
#pragma unroll
    for (int i = 0; i < 4; ++i) {
        int c = ty + i * 8;
        float v = tb[tx][c];
        __nv_bfloat16 hi, lo;
        split2(v, hi, lo);
        oh[(long)(c0 + c) * ldo + r0 + tx] = hi;
        ol[(long)(c0 + c) * ldo + r0 + tx] = lo;
    }
}

__global__ void zero_kernel(float4* __restrict__ p, long n4) {
    long i = (long)blockIdx.x * 256 + threadIdx.x;
    if (i < n4) p[i] = make_float4(0.f, 0.f, 0.f, 0.f);
}

// ---------- CSR build ----------
__global__ void count_kernel(const int* __restrict__ knn) {
    int e = blockIdx.x * 256 + threadIdx.x;
    int srow = e / Kk;
    int b = srow >> 13;
    atomicAdd(&g_deg[(b << 13) + knn[e]], 1);
}

__global__ void scan1() {
    int b = blockIdx.x, t = threadIdx.x;
    int v = g_deg[b * 1024 + t];
    v = (int)warp_sum((float)v);
    __shared__ int sh[32];
    if ((t & 31) == 0) sh[t >> 5] = v;
    __syncthreads();
    if (t == 0) {
        int s = 0;
#pragma unroll
        for (int i = 0; i < 32; i++) s += sh[i];
        g_part[b] = s;
    }
}
__global__ void scan2() {
    int run = 0;
    for (int i = 0; i < 64; i++) { g_partoff[i] = run; run += g_part[i]; }
}
__global__ void scan3() {
    __shared__ int sh[1024];
    int b = blockIdx.x, t = threadIdx.x;
    int v = g_deg[b * 1024 + t];
    sh[t] = v;
    __syncthreads();
#pragma unroll
    for (int off = 1; off < 1024; off <<= 1) {
        int x = (t >= off) ? sh[t - off] : 0;
        __syncthreads();
        sh[t] += x;
        __syncthreads();
    }
    int incl = sh[t];
    g_rowstart[b * 1024 + t] = g_partoff[b] + incl - v;
    if (b == 63 && t == 1023) g_rowstart[BN] = g_partoff[b] + incl;
}

__global__ void fill_kernel(const int* __restrict__ knn) {
    int e = blockIdx.x * 256 + threadIdx.x;
    int srow = e / Kk;
    int b = srow >> 13;
    int dst = (b << 13) + knn[e];
    int pos = g_rowstart[dst] + atomicAdd(&g_cursor[dst], 1);
    g_csr_src[pos] = srow;
}

// ---------- fused k/v gather hop: float4 loads, column-chunked ----------
__global__ void gather2(const float* __restrict__ s1, const float* __restrict__ s2, int sld,
                        float scale, float* __restrict__ d1, float* __restrict__ d2) {
    int j = blockIdx.x;
    int t4 = (blockIdx.y << 5) + threadIdx.x;
    int s = g_rowstart[j], e = g_rowstart[j + 1];
    float4 a1 = make_float4(0.f, 0.f, 0.f, 0.f);
    float4 a2 = make_float4(0.f, 0.f, 0.f, 0.f);
    for (int p = s; p < e; ++p) {
        long n = g_csr_src[p];
        float4 v1 = *(const float4*)(s1 + n * sld + (t4 << 2));
        float4 v2 = *(const float4*)(s2 + n * sld + (t4 << 2));
        a1.x += v1.x; a1.y += v1.y; a1.z += v1.z; a1.w += v1.w;
        a2.x += v2.x; a2.y += v2.y; a2.z += v2.z; a2.w += v2.w;
    }
    a1.x *= scale; a1.y *= scale; a1.z *= scale; a1.w *= scale;
    a2.x *= scale; a2.y *= scale; a2.z *= scale; a2.w *= scale;
    *(float4*)(d1 + (long)j * Dd + (t4 << 2)) = a1;
    *(float4*)(d2 + (long)j * Dd + (t4 << 2)) = a2;
}

// ---------- FUSED hop-3 gather + attn scalar + split (float4, block 64) ----------
__global__ void gather_attnsplit(const float* __restrict__ vb, const float* __restrict__ kb,
                                 float scale) {
    int row = blockIdx.x, t4 = threadIdx.x;
    int s = g_rowstart[row], e = g_rowstart[row + 1];
    float4 av = make_float4(0.f, 0.f, 0.f, 0.f);
    float4 ak = make_float4(0.f, 0.f, 0.f, 0.f);
    for (int p = s; p < e; ++p) {
        long n = g_csr_src[p];
        float4 v = *(const float4*)(vb + n * Dd + (t4 << 2));
        float4 k = *(const float4*)(kb + n * Dd + (t4 << 2));
        av.x += v.x; av.y += v.y; av.z += v.z; av.w += v.w;
        ak.x += k.x; ak.y += k.y; ak.z += k.z; ak.w += k.w;
    }
    av.x *= scale; av.y *= scale; av.z *= scale; av.w *= scale;
    ak.x *= scale; ak.y *= scale; ak.z *= scale; ak.w *= scale;
    float4 q = *(const float4*)(&g_qkv[(size_t)row * QLD + (t4 << 2)]);
    float pr = q.x * ak.x + q.y * ak.y + q.z * ak.z + q.w * ak.w;
    pr = warp_sum(pr);
    __shared__ float sh[2];
    int w = t4 >> 5, l = t4 & 31;
    if (l == 0) sh[w] = pr;
    __syncthreads();
    float sdot = sh[0] + sh[1];
    float vv[4] = {av.x * sdot, av.y * sdot, av.z * sdot, av.w * sdot};
    size_t base = (size_t)row * Dd + (t4 << 2);
#pragma unroll
    for (int i = 0; i < 4; ++i) {
        __nv_bfloat16 hi, lo;
        split2(vv[i], hi, lo);
        g_a_hi[base + i] = hi;
        g_a_lo[base + i] = lo;
    }
}

__global__ void ksum_kernel() {
    int b = blockIdx.x >> 7, chunk = blockIdx.x & 127;
    int d = threadIdx.x;
    float s = 0.f;
    size_t base = ((size_t)b * Nn + (size_t)chunk * 64) * QLD + Dd + d;
    for (int r = 0; r < 64; r++) s += g_qkv[base + (size_t)r * QLD];
    atomicAdd(&g_ksum[b * Dd + d], s);
}

__global__ void zcalc_kernel() {
    long gt = (long)blockIdx.x * 256 + threadIdx.x;
    int row = (int)(gt >> 5), lane = (int)(gt & 31);
    int b = row >> 13;
    float s = 0.f;
#pragma unroll
    for (int it = 0; it < 8; it++) {
        int d = it * 32 + lane;
        s += g_qkv[(size_t)row * QLD + d] * g_ksum[b * Dd + d];
    }
    s = warp_sum(s);
    if (lane == 0) g_scal[row] = 1.0f / (s + 1e-6f);
}

__global__ void head_kernel(const float* __restrict__ w, const float* __restrict__ hb,
                            float* __restrict__ out) {
    long gt = (long)blockIdx.x * 256 + threadIdx.x;
    int row = (int)(gt >> 5), lane = (int)(gt & 31);
    float a0 = 0.f, a1 = 0.f, a2 = 0.f;
#pragma unroll
    for (int it = 0; it < 8; it++) {
        int d = it * 32 + lane;
        float hv = g_h[(size_t)row * Dd + d];
        a0 += hv * w[d * 3 + 0];
        a1 += hv * w[d * 3 + 1];
        a2 += hv * w[d * 3 + 2];
    }
    a0 = warp_sum(a0); a1 = warp_sum(a1); a2 = warp_sum(a2);
    if (lane == 0) {
        out[(size_t)row * 3 + 0] = a0 + hb[0];
        out[(size_t)row * 3 + 1] = a1 + hb[1];
        out[(size_t)row * 3 + 2] = a2 + hb[2];
    }
}

// ===================== host =====================
extern "C" void kernel_launch(void* const* d_in, const int* in_sizes, int n_in,
                              void* d_out, int out_size) {
    const float* x        = (const float*)d_in[0];
    const int*   knn      = (const int*)  d_in[1];
    const float* emb_w    = (const float*)d_in[2];
    const float* emb_b    = (const float*)d_in[3];
    const float* norm_g   = (const float*)d_in[4];
    const float* norm_b   = (const float*)d_in[5];
    const float* grf_qkv  = (const float*)d_in[6];
    const float* grf_outw = (const float*)d_in[7];
    const float* grf_outb = (const float*)d_in[8];
    const float* attn_qkv = (const float*)d_in[9];
    const float* attn_outw= (const float*)d_in[10];
    const float* attn_outb= (const float*)d_in[11];
    const float* head_w   = (const float*)d_in[12];
    const float* head_b   = (const float*)d_in[13];
    float* out = (float*)d_out;

    static int smem_set = 0;
    if (!smem_set) {
        cudaFuncSetAttribute(tc_gemm, cudaFuncAttributeMaxDynamicSharedMemorySize, SM_GEMM);
        smem_set = 1;
    }

    float *h, *qkv, *va, *vb, *ka, *kb, *scal, *kvm, *ksum;
    int *deg, *cursor;
    cudaGetSymbolAddress((void**)&h,    g_h);
    cudaGetSymbolAddress((void**)&qkv,  g_qkv);
    cudaGetSymbolAddress((void**)&va,   g_va);
    cudaGetSymbolAddress((void**)&vb,   g_vb);
    cudaGetSymbolAddress((void**)&ka,   g_ka);
    cudaGetSymbolAddress((void**)&kb,   g_kb);
    cudaGetSymbolAddress((void**)&scal, g_scal);
    cudaGetSymbolAddress((void**)&kvm,  g_kvm);
    cudaGetSymbolAddress((void**)&ksum, g_ksum);
    cudaGetSymbolAddress((void**)&deg,    g_deg);
    cudaGetSymbolAddress((void**)&cursor, g_cursor);
    __nv_bfloat16 *hnh, *hnl, *ah, *al, *vbh, *vbl, *kth, *ktl, *vth, *vtl, *kvth, *kvtl;
    __nv_bfloat16 *wgqh, *wgql, *waqh, *waql, *wgoh, *wgol, *waoh, *waol;
    cudaGetSymbolAddress((void**)&hnh, g_hn_hi); cudaGetSymbolAddress((void**)&hnl, g_hn_lo);
    cudaGetSymbolAddress((void**)&ah,  g_a_hi);  cudaGetSymbolAddress((void**)&al,  g_a_lo);
    cudaGetSymbolAddress((void**)&vbh, g_vbh);   cudaGetSymbolAddress((void**)&vbl, g_vbl);
    cudaGetSymbolAddress((void**)&kth, g_kT_hi); cudaGetSymbolAddress((void**)&ktl, g_kT_lo);
    cudaGetSymbolAddress((void**)&vth, g_vT_hi); cudaGetSymbolAddress((void**)&vtl, g_vT_lo);
    cudaGetSymbolAddress((void**)&kvth, g_kvT_hi); cudaGetSymbolAddress((void**)&kvtl, g_kvT_lo);
    cudaGetSymbolAddress((void**)&wgqh, g_wgq_hi); cudaGetSymbolAddress((void**)&wgql, g_wgq_lo);
    cudaGetSymbolAddress((void**)&waqh, g_waq_hi); cudaGetSymbolAddress((void**)&waql, g_waq_lo);
    cudaGetSymbolAddress((void**)&wgoh, g_wgo_hi); cudaGetSymbolAddress((void**)&wgol, g_wgo_lo);
    cudaGetSymbolAddress((void**)&waoh, g_wao_hi); cudaGetSymbolAddress((void**)&waol, g_wao_lo);

    const float s_hop = 1.0f / ((float)Kk + 1e-6f);
    const int egrid = BN * Kk / 256;

    // ---- front-loaded so tc_gemm is launch #4 (ncu capture target) ----
    tsplit<<<dim3(24, 8, Ll), 256>>>(grf_qkv, QLD, (long)Dd * QLD, wgqh, wgql, Dd, (long)QLD * Dd);
    embed_kernel<<<BN, Dd>>>(x, emb_w, emb_b);
    ln_kernel<<<BN, Dd>>>(norm_g, norm_b);
    tc_gemm<<<dim3(512, 3, 1), 512, SM_GEMM>>>(
        hnh, hnl, Dd, 0, wgqh, wgql, Dd, 0,
        1, 8, qkv, QLD, 0, nullptr, nullptr, nullptr, nullptr, 0, 0, 0, 1);

    // ---- CSR build (needed before first gather) ----
    zero_kernel<<<BN / 1024, 256>>>((float4*)deg, BN / 4);
    zero_kernel<<<BN / 1024, 256>>>((float4*)cursor, BN / 4);
    count_kernel<<<egrid, 256>>>(knn);
    scan1<<<64, 1024>>>();
    scan2<<<1, 1>>>();
    scan3<<<64, 1024>>>();
    fill_kernel<<<egrid, 256>>>(knn);

    // ---- remaining weight transpose + split ----
    tsplit<<<dim3(24, 8, Ll), 256>>>(attn_qkv, QLD, (long)Dd * QLD, waqh, waql, Dd, (long)QLD * Dd);
    tsplit<<<dim3(8, 8, Ll), 256>>>(grf_outw, Dd, (long)Dd * Dd, wgoh, wgol, Dd, (long)Dd * Dd);
    tsplit<<<dim3(8, 8, Ll), 256>>>(attn_outw, Dd, (long)Dd * Dd, waoh, waol, Dd, (long)Dd * Dd);

    for (int i = 0; i < Ll; i++) {
        // ===== GRF block =====
        if (i > 0) {
            ln_kernel<<<BN, Dd>>>(norm_g + (size_t)(2 * i) * Dd, norm_b + (size_t)(2 * i) * Dd);
            tc_gemm<<<dim3(512, 3, 1), 512, SM_GEMM>>>(
                hnh, hnl, Dd, 0, wgqh + (size_t)i * QLD * Dd, wgql + (size_t)i * QLD * Dd, Dd, 0,
                1, 8, qkv, QLD, 0, nullptr, nullptr, nullptr, nullptr, 0, 0, 0, 1);
        }
        gather2<<<dim3(BN, 2), 32>>>(qkv + 2 * Dd, qkv + Dd, QLD, s_hop, va, ka);
        gather2<<<dim3(BN, 2), 32>>>(va, ka, Dd, s_hop, vb, kb);
        gather_attnsplit<<<BN, 64>>>(vb, kb, s_hop);
        tc_gemm<<<dim3(512, 1, 1), 512, SM_GEMM>>>(
            ah, al, Dd, 0, wgoh + (size_t)i * Dd * Dd, wgol + (size_t)i * Dd * Dd, Dd, 0,
            1, 8, h, Dd, 0, grf_outb + (size_t)i * Dd, nullptr, nullptr, nullptr, 0, 0, 0, 2);

        // ===== linear attention block =====
        ln_kernel<<<BN, Dd>>>(norm_g + (size_t)(2 * i + 1) * Dd, norm_b + (size_t)(2 * i + 1) * Dd);
        tc_gemm<<<dim3(512, 3, 1), 512, SM_GEMM>>>(
            hnh, hnl, Dd, 0, waqh + (size_t)i * QLD * Dd, waql + (size_t)i * QLD * Dd, Dd, 0,
            1, 8, qkv, QLD, 0, nullptr, nullptr, ah, al, Dd, 2 * Dd, Dd, 1 | 8);
        zero_kernel<<<2, 256>>>((float4*)ksum, (long)Bc * Dd / 4);
        ksum_kernel<<<Bc * 128, 256>>>();
        tsplit<<<dim3(8, 256, Bc), 256>>>(qkv + Dd, QLD, (long)Nn * QLD, kth, ktl, Nn, (long)Dd * Nn);
        tsplit<<<dim3(8, 256, Bc), 256>>>(qkv + 2 * Dd, QLD, (long)Nn * QLD, vth, vtl, Nn, (long)Dd * Nn);
        zero_kernel<<<(Bc * Dd * Dd / 4 + 255) / 256, 256>>>((float4*)kvm, (long)Bc * Dd * Dd / 4);
        tc_gemm<<<dim3(2, 1, Bc * 16), 512, SM_GEMM>>>(
            kth, ktl, Nn, Dd, vth, vtl, Nn, Dd,
            16, 16, kvm, Dd, Dd, nullptr, nullptr, nullptr, nullptr, 0, 0, 0, 4);
        zcalc_kernel<<<BN * 32 / 256, 256>>>();
        tsplit<<<dim3(8, 8, Bc), 256>>>(kvm, Dd, (long)Dd * Dd, kvth, kvtl, Dd, (long)Dd * Dd);
        tc_gemm<<<dim3(64, 1, Bc), 512, SM_GEMM>>>(
            ah, al, Dd, Nn, kvth, kvtl, Dd, Dd,
            1, 8, nullptr, 0, Nn, nullptr, scal, vbh, vbl, Dd, 0, Dd, 8);
        tc_gemm<<<dim3(512, 1, 1), 512, SM_GEMM>>>(
            vbh, vbl, Dd, 0, waoh + (size_t)i * Dd * Dd, waol + (size_t)i * Dd * Dd, Dd, 0,
            1, 8, h, Dd, 0, attn_outb + (size_t)i * Dd, nullptr, nullptr, nullptr, 0, 0, 0, 2);
    }

    head_kernel<<<BN * 32 / 256, 256>>>(head_w, head_b, out);
}

// round 14
// speedup vs baseline: 1.1677x; 1.1677x over previous
#include <cuda_runtime.h>
#include <cuda_bf16.h>
#include <cstdint>

#define Bc 8
#define Nn 8192
#define Kk 6
#define Dd 256
#define Ll 5
#define BN 65536
#define QLD 768

// ===================== device scratch =====================
__device__ float g_h  [(size_t)BN * Dd];
__device__ float g_qkv[(size_t)BN * 3 * Dd];
__device__ float g_va [(size_t)BN * Dd];
__device__ float g_vb [(size_t)BN * Dd];
__device__ float g_ka [(size_t)BN * Dd];
__device__ float g_kb [(size_t)BN * Dd];
__device__ float g_scal[BN];
__device__ float g_kvm [Bc * Dd * Dd];
__device__ float g_ksum[Bc * Dd];

// CSR (transposed adjacency)
__device__ int g_deg[BN];
__device__ int g_cursor[BN];
__device__ int g_rowstart[BN + 1];
__device__ int g_csr_src[BN * Kk];
__device__ int g_part[64];
__device__ int g_partoff[64];

__device__ __align__(128) __nv_bfloat16 g_hn_hi[(size_t)BN * Dd], g_hn_lo[(size_t)BN * Dd];
__device__ __align__(128) __nv_bfloat16 g_a_hi [(size_t)BN * Dd], g_a_lo [(size_t)BN * Dd];
__device__ __align__(128) __nv_bfloat16 g_vbh  [(size_t)BN * Dd], g_vbl  [(size_t)BN * Dd];
__device__ __align__(128) __nv_bfloat16 g_kT_hi[(size_t)Bc * Dd * Nn], g_kT_lo[(size_t)Bc * Dd * Nn];
__device__ __align__(128) __nv_bfloat16 g_vT_hi[(size_t)Bc * Dd * Nn], g_vT_lo[(size_t)Bc * Dd * Nn];
__device__ __align__(128) __nv_bfloat16 g_kvT_hi[Bc * Dd * Dd], g_kvT_lo[Bc * Dd * Dd];
__device__ __align__(128) __nv_bfloat16 g_wgq_hi[Ll * 3 * Dd * Dd], g_wgq_lo[Ll * 3 * Dd * Dd];
__device__ __align__(128) __nv_bfloat16 g_waq_hi[Ll * 3 * Dd * Dd], g_waq_lo[Ll * 3 * Dd * Dd];
__device__ __align__(128) __nv_bfloat16 g_wgo_hi[Ll * Dd * Dd],     g_wgo_lo[Ll * Dd * Dd];
__device__ __align__(128) __nv_bfloat16 g_wao_hi[Ll * Dd * Dd],     g_wao_lo[Ll * Dd * Dd];

// ===================== PTX helpers (base PTX, sm_103-legal) ============
__device__ __forceinline__ uint32_t smem_to_u32(const void* p) {
    uint32_t a;
    asm("{ .reg .u64 t; cvta.to.shared.u64 t, %1; cvt.u32.u64 %0, t; }" : "=r"(a) : "l"(p));
    return a;
}
#define LDSM_X4(r0, r1, r2, r3, addr) \
    asm volatile("ldmatrix.sync.aligned.m8n8.x4.shared.b16 {%0,%1,%2,%3}, [%4];" \
        : "=r"(r0), "=r"(r1), "=r"(r2), "=r"(r3) : "r"(addr))
#define MMA_BF16(d, a, b) \
    asm volatile("mma.sync.aligned.m16n8k16.row.col.f32.bf16.bf16.f32 " \
        "{%0,%1,%2,%3}, {%4,%5,%6,%7}, {%8,%9}, {%0,%1,%2,%3};" \
        : "+f"((d)[0]), "+f"((d)[1]), "+f"((d)[2]), "+f"((d)[3]) \
        : "r"((a)[0]), "r"((a)[1]), "r"((a)[2]), "r"((a)[3]), "r"((b)[0]), "r"((b)[1]))
#define CP_ASYNC16(s, g) \
    asm volatile("cp.async.cg.shared.global [%0], [%1], 16;" :: "r"(s), "l"(g))
#define CP_COMMIT() asm volatile("cp.async.commit_group;" ::: "memory")
#define CP_WAIT0()  asm volatile("cp.async.wait_group 0;" ::: "memory")

__device__ __forceinline__ void split2(float v, __nv_bfloat16& hi, __nv_bfloat16& lo) {
    hi = __float2bfloat16(v);
    lo = __float2bfloat16(v - __bfloat162float(hi));
}

// ===================== tensor-core GEMM (R12 proven config — FROZEN) ==========
// 8 warps, CTA tile 128x128, warp tile 64x32, split-bf16 3-term.
// flags: 1 store fp32, 2 add fp32, 4 atomicAdd fp32, 8 store bf16-split (n<bf16Limit),
//        16 store fp32 only for n>=bf16Limit
#define STG 40960
#define SM_GEMM 81920

__global__ __launch_bounds__(256, 2) void tc_gemm(
    const __nv_bfloat16* __restrict__ Ah, const __nv_bfloat16* __restrict__ Al, int lda, int aBatchRows,
    const __nv_bfloat16* __restrict__ Bh, const __nv_bfloat16* __restrict__ Bl, int ldb, int bBatchRows,
    int nsplit, int kChunks,
    float* __restrict__ C, int ldc, int cBatchRows,
    const float* __restrict__ bias, const float* __restrict__ rowscale,
    __nv_bfloat16* __restrict__ Oh, __nv_bfloat16* __restrict__ Ol, int ldo,
    int reluLimit, int bf16Limit, int flags)
{
    extern __shared__ char dsm[];
    uint32_t sb = smem_to_u32(dsm);
    int t = threadIdx.x, wid = t >> 5, lane = t & 31;
    int batch = blockIdx.z / nsplit, ks = blockIdx.z % nsplit;
    int m0 = blockIdx.x * 128, n0 = blockIdx.y * 128;
    int kBase = ks * kChunks * 32;
    long aRow0 = (long)batch * aBatchRows + m0;
    long bRow0 = (long)batch * bBatchRows + n0;
    int wm = (wid & 1) * 64;
    int wn = (wid >> 1) * 32;

    float acc[4][4][4];
#pragma unroll
    for (int i = 0; i < 4; i++)
#pragma unroll
        for (int j = 0; j < 4; j++)
#pragma unroll
            for (int r = 0; r < 4; r++) acc[i][j][r] = 0.f;

    int lr = t >> 2, seg = t & 3;

#define LOAD_STAGE(c, st) do { \
        int kb = kBase + (c) * 32; \
        uint32_t sbase = sb + (st) * STG; \
        _Pragma("unroll") \
        for (int rr = 0; rr < 2; ++rr) { \
            int row = lr + rr * 64; \
            long ao = (aRow0 + row) * (long)lda + kb + seg * 8; \
            long bo = (bRow0 + row) * (long)ldb + kb + seg * 8; \
            uint32_t so = (uint32_t)row * 80 + seg * 16; \
            CP_ASYNC16(sbase + so,         (const char*)(Ah + ao)); \
            CP_ASYNC16(sbase + 10240 + so, (const char*)(Al + ao)); \
            CP_ASYNC16(sbase + 20480 + so, (const char*)(Bh + bo)); \
            CP_ASYNC16(sbase + 30720 + so, (const char*)(Bl + bo)); \
        } \
        CP_COMMIT(); \
    } while (0)

    LOAD_STAGE(0, 0);

    for (int c = 0; c < kChunks; ++c) {
        int st = c & 1;
        CP_WAIT0();
        __syncthreads();
        if (c + 1 < kChunks) LOAD_STAGE(c + 1, (c + 1) & 1);

        uint32_t uAh = sb + st * STG, uAl = uAh + 10240;
        uint32_t uBh = uAh + 20480,   uBl = uAh + 30720;
#pragma unroll
        for (int kk = 0; kk < 2; ++kk) {
            int kbb = kk * 16;
            uint32_t ah[4][4], al[4][4], bh[4][2], bl[4][2];
            int arow = (lane & 7) + ((lane >> 3) & 1) * 8;
            int acol = kbb + (lane >> 4) * 8;
#pragma unroll
            for (int mt = 0; mt < 4; ++mt) {
                uint32_t off = (uint32_t)(wm + mt * 16 + arow) * 80 + acol * 2;
                LDSM_X4(ah[mt][0], ah[mt][1], ah[mt][2], ah[mt][3], uAh + off);
                LDSM_X4(al[mt][0], al[mt][1], al[mt][2], al[mt][3], uAl + off);
            }
            int brow = (lane & 7) + ((lane >> 4) & 1) * 8;
            int bcol = kbb + ((lane >> 3) & 1) * 8;
#pragma unroll
            for (int p = 0; p < 2; ++p) {
                uint32_t off = (uint32_t)(wn + p * 16 + brow) * 80 + bcol * 2;
                LDSM_X4(bh[2 * p][0], bh[2 * p][1], bh[2 * p + 1][0], bh[2 * p + 1][1], uBh + off);
                LDSM_X4(bl[2 * p][0], bl[2 * p][1], bl[2 * p + 1][0], bl[2 * p + 1][1], uBl + off);
            }
#pragma unroll
            for (int mt = 0; mt < 4; ++mt)
#pragma unroll
                for (int nt = 0; nt < 4; ++nt) {
                    MMA_BF16(acc[mt][nt], ah[mt], bh[nt]);
                    MMA_BF16(acc[mt][nt], ah[mt], bl[nt]);
                    MMA_BF16(acc[mt][nt], al[mt], bh[nt]);
                }
        }
    }

    // epilogue
#pragma unroll
    for (int mt = 0; mt < 4; ++mt) {
        int r0g = m0 + wm + mt * 16 + (lane >> 2);
        long row0 = (long)batch * cBatchRows + r0g;
        long row1 = row0 + 8;
        float rs0 = rowscale ? rowscale[row0] : 1.f;
        float rs1 = rowscale ? rowscale[row1] : 1.f;
#pragma unroll
        for (int nt = 0; nt < 4; ++nt) {
            int c0 = n0 + wn + nt * 8 + (lane & 3) * 2;
#pragma unroll
            for (int half = 0; half < 2; ++half) {
                long row = half ? row1 : row0;
                float rs = half ? rs1 : rs0;
#pragma unroll
                for (int cc = 0; cc < 2; ++cc) {
                    float v = acc[mt][nt][half * 2 + cc] * rs;
                    int n = c0 + cc;
                    if (n < reluLimit) v = fmaxf(v, 0.f) + 1e-6f;
                    if (bias) v += bias[n];
                    if (flags & 1) C[row * ldc + n] = v;
                    if (flags & 2) C[row * ldc + n] += v;
                    if (flags & 4) atomicAdd(&C[row * ldc + n], v);
                    if ((flags & 16) && n >= bf16Limit) C[row * ldc + n] = v;
                    if ((flags & 8) && n < bf16Limit) {
                        __nv_bfloat16 hi, lo;
                        split2(v, hi, lo);
                        Oh[row * ldo + n] = hi;
                        Ol[row * ldo + n] = lo;
                    }
                }
            }
        }
    }
}

// ===================== SIMT kernels =====================
__device__ __forceinline__ float warp_sum(float v) {
#pragma unroll
    for (int o = 16; o > 0; o >>= 1) v += __shfl_xor_sync(0xffffffffu, v, o);
    return v;
}

__global__ void embed_kernel(const float* __restrict__ x, const float* __restrict__ w,
                             const float* __restrict__ b) {
    int row = blockIdx.x, t = threadIdx.x;
    float x0 = x[row * 3], x1 = x[row * 3 + 1], x2 = x[row * 3 + 2];
    g_h[(size_t)row * Dd + t] = b[t] + x0 * w[t] + x1 * w[Dd + t] + x2 * w[2 * Dd + t];
}

__global__ void ln_kernel(const float* __restrict__ g, const float* __restrict__ b) {
    int row = blockIdx.x, t = threadIdx.x;
    float x = g_h[(size_t)row * Dd + t];
    float s = warp_sum(x), s2 = warp_sum(x * x);
    __shared__ float sh1[8], sh2[8];
    int w = t >> 5, l = t & 31;
    if (l == 0) { sh1[w] = s; sh2[w] = s2; }
    __syncthreads();
    if (t == 0) {
        float a = 0.f, c = 0.f;
#pragma unroll
        for (int i = 0; i < 8; i++) { a += sh1[i]; c += sh2[i]; }
        sh1[0] = a; sh2[0] = c;
    }
    __syncthreads();
    float m = sh1[0] * (1.0f / Dd);
    float var = fmaxf(sh2[0] * (1.0f / Dd) - m * m, 0.0f);
    float inv = rsqrtf(var + 1e-5f);
    float y = (x - m) * inv * g[t] + b[t];
    __nv_bfloat16 hi, lo;
    split2(y, hi, lo);
    g_hn_hi[(size_t)row * Dd + t] = hi;
    g_hn_lo[(size_t)row * Dd + t] = lo;
}

__global__ void tsplit(const float* __restrict__ in, int ldi, long inB,
                       __nv_bfloat16* __restrict__ oh, __nv_bfloat16* __restrict__ ol,
                       int ldo, long oB) {
    int z = blockIdx.z;
    in += (long)z * inB; oh += (long)z * oB; ol += (long)z * oB;
    __shared__ float tb[32][33];
    int c0 = blockIdx.x * 32, r0 = blockIdx.y * 32;
    int tx = threadIdx.x & 31, ty = threadIdx.x >> 5;
#pragma unroll
    for (int i = 0; i < 4; ++i) {
        int r = ty + i * 8;
        tb[r][tx] = in[(long)(r0 + r) * ldi + c0 + tx];
    }
    __syncthreads();
#pragma unroll
    for (int i = 0; i < 4; ++i) {
        int c = ty + i * 8;
        float v = tb[tx][c];
        __nv_bfloat16 hi, lo;
        split2(v, hi, lo);
        oh[(long)(c0 + c) * ldo + r0 + tx] = hi;
        ol[(long)(c0 + c) * ldo + r0 + tx] = lo;
    }
}

__global__ void zero_kernel(float4* __restrict__ p, long n4) {
    long i = (long)blockIdx.x * 256 + threadIdx.x;
    if (i < n4) p[i] = make_float4(0.f, 0.f, 0.f, 0.f);
}

// ---------- CSR build ----------
__global__ void count_kernel(const int* __restrict__ knn) {
    int e = blockIdx.x * 256 + threadIdx.x;
    int srow = e / Kk;
    int b = srow >> 13;
    atomicAdd(&g_deg[(b << 13) + knn[e]], 1);
}

__global__ void scan1() {
    int b = blockIdx.x, t = threadIdx.x;
    int v = g_deg[b * 1024 + t];
    v = (int)warp_sum((float)v);
    __shared__ int sh[32];
    if ((t & 31) == 0) sh[t >> 5] = v;
    __syncthreads();
    if (t == 0) {
        int s = 0;
#pragma unroll
        for (int i = 0; i < 32; i++) s += sh[i];
        g_part[b] = s;
    }
}
__global__ void scan2() {
    int run = 0;
    for (int i = 0; i < 64; i++) { g_partoff[i] = run; run += g_part[i]; }
}
__global__ void scan3() {
    __shared__ int sh[1024];
    int b = blockIdx.x, t = threadIdx.x;
    int v = g_deg[b * 1024 + t];
    sh[t] = v;
    __syncthreads();
#pragma unroll
    for (int off = 1; off < 1024; off <<= 1) {
        int x = (t >= off) ? sh[t - off] : 0;
        __syncthreads();
        sh[t] += x;
        __syncthreads();
    }
    int incl = sh[t];
    g_rowstart[b * 1024 + t] = g_partoff[b] + incl - v;
    if (b == 63 && t == 1023) g_rowstart[BN] = g_partoff[b] + incl;
}

__global__ void fill_kernel(const int* __restrict__ knn) {
    int e = blockIdx.x * 256 + threadIdx.x;
    int srow = e / Kk;
    int b = srow >> 13;
    int dst = (b << 13) + knn[e];
    int pos = g_rowstart[dst] + atomicAdd(&g_cursor[dst], 1);
    g_csr_src[pos] = srow;
}

// ---------- fused k/v gather hop: float4 loads, column-chunked ----------
__global__ void gather2(const float* __restrict__ s1, const float* __restrict__ s2, int sld,
                        float scale, float* __restrict__ d1, float* __restrict__ d2) {
    int j = blockIdx.x;
    int t4 = (blockIdx.y << 5) + threadIdx.x;
    int s = g_rowstart[j], e = g_rowstart[j + 1];
    float4 a1 = make_float4(0.f, 0.f, 0.f, 0.f);
    float4 a2 = make_float4(0.f, 0.f, 0.f, 0.f);
    for (int p = s; p < e; ++p) {
        long n = g_csr_src[p];
        float4 v1 = *(const float4*)(s1 + n * sld + (t4 << 2));
        float4 v2 = *(const float4*)(s2 + n * sld + (t4 << 2));
        a1.x += v1.x; a1.y += v1.y; a1.z += v1.z; a1.w += v1.w;
        a2.x += v2.x; a2.y += v2.y; a2.z += v2.z; a2.w += v2.w;
    }
    a1.x *= scale; a1.y *= scale; a1.z *= scale; a1.w *= scale;
    a2.x *= scale; a2.y *= scale; a2.z *= scale; a2.w *= scale;
    *(float4*)(d1 + (long)j * Dd + (t4 << 2)) = a1;
    *(float4*)(d2 + (long)j * Dd + (t4 << 2)) = a2;
}

// ---------- FUSED hop-3 gather + attn scalar + split (float4, block 64) ----------
__global__ void gather_attnsplit(const float* __restrict__ vb, const float* __restrict__ kb,
                                 float scale) {
    int row = blockIdx.x, t4 = threadIdx.x;
    int s = g_rowstart[row], e = g_rowstart[row + 1];
    float4 av = make_float4(0.f, 0.f, 0.f, 0.f);
    float4 ak = make_float4(0.f, 0.f, 0.f, 0.f);
    for (int p = s; p < e; ++p) {
        long n = g_csr_src[p];
        float4 v = *(const float4*)(vb + n * Dd + (t4 << 2));
        float4 k = *(const float4*)(kb + n * Dd + (t4 << 2));
        av.x += v.x; av.y += v.y; av.z += v.z; av.w += v.w;
        ak.x += k.x; ak.y += k.y; ak.z += k.z; ak.w += k.w;
    }
    av.x *= scale; av.y *= scale; av.z *= scale; av.w *= scale;
    ak.x *= scale; ak.y *= scale; ak.z *= scale; ak.w *= scale;
    float4 q = *(const float4*)(&g_qkv[(size_t)row * QLD + (t4 << 2)]);
    float pr = q.x * ak.x + q.y * ak.y + q.z * ak.z + q.w * ak.w;
    pr = warp_sum(pr);
    __shared__ float sh[2];
    int w = t4 >> 5, l = t4 & 31;
    if (l == 0) sh[w] = pr;
    __syncthreads();
    float sdot = sh[0] + sh[1];
    float vv[4] = {av.x * sdot, av.y * sdot, av.z * sdot, av.w * sdot};
    size_t base = (size_t)row * Dd + (t4 << 2);
#pragma unroll
    for (int i = 0; i < 4; ++i) {
        __nv_bfloat16 hi, lo;
        split2(vv[i], hi, lo);
        g_a_hi[base + i] = hi;
        g_a_lo[base + i] = lo;
    }
}

__global__ void ksum_kernel() {
    int b = blockIdx.x >> 7, chunk = blockIdx.x & 127;
    int d = threadIdx.x;
    float s = 0.f;
    size_t base = ((size_t)b * Nn + (size_t)chunk * 64) * QLD + Dd + d;
    for (int r = 0; r < 64; r++) s += g_qkv[base + (size_t)r * QLD];
    atomicAdd(&g_ksum[b * Dd + d], s);
}

// z from bf16-split q (q fp32 no longer stored)
__global__ void zcalc_kernel() {
    long gt = (long)blockIdx.x * 256 + threadIdx.x;
    int row = (int)(gt >> 5), lane = (int)(gt & 31);
    int b = row >> 13;
    float s = 0.f;
#pragma unroll
    for (int it = 0; it < 8; it++) {
        int d = it * 32 + lane;
        float q = __bfloat162float(g_a_hi[(size_t)row * Dd + d]) +
                  __bfloat162float(g_a_lo[(size_t)row * Dd + d]);
        s += q * g_ksum[b * Dd + d];
    }
    s = warp_sum(s);
    if (lane == 0) g_scal[row] = 1.0f / (s + 1e-6f);
}

__global__ void head_kernel(const float* __restrict__ w, const float* __restrict__ hb,
                            float* __restrict__ out) {
    long gt = (long)blockIdx.x * 256 + threadIdx.x;
    int row = (int)(gt >> 5), lane = (int)(gt & 31);
    float a0 = 0.f, a1 = 0.f, a2 = 0.f;
#pragma unroll
    for (int it = 0; it < 8; it++) {
        int d = it * 32 + lane;
        float hv = g_h[(size_t)row * Dd + d];
        a0 += hv * w[d * 3 + 0];
        a1 += hv * w[d * 3 + 1];
        a2 += hv * w[d * 3 + 2];
    }
    a0 = warp_sum(a0); a1 = warp_sum(a1); a2 = warp_sum(a2);
    if (lane == 0) {
        out[(size_t)row * 3 + 0] = a0 + hb[0];
        out[(size_t)row * 3 + 1] = a1 + hb[1];
        out[(size_t)row * 3 + 2] = a2 + hb[2];
    }
}

// ===================== host =====================
extern "C" void kernel_launch(void* const* d_in, const int* in_sizes, int n_in,
                              void* d_out, int out_size) {
    const float* x        = (const float*)d_in[0];
    const int*   knn      = (const int*)  d_in[1];
    const float* emb_w    = (const float*)d_in[2];
    const float* emb_b    = (const float*)d_in[3];
    const float* norm_g   = (const float*)d_in[4];
    const float* norm_b   = (const float*)d_in[5];
    const float* grf_qkv  = (const float*)d_in[6];
    const float* grf_outw = (const float*)d_in[7];
    const float* grf_outb = (const float*)d_in[8];
    const float* attn_qkv = (const float*)d_in[9];
    const float* attn_outw= (const float*)d_in[10];
    const float* attn_outb= (const float*)d_in[11];
    const float* head_w   = (const float*)d_in[12];
    const float* head_b   = (const float*)d_in[13];
    float* out = (float*)d_out;

    static int smem_set = 0;
    if (!smem_set) {
        cudaFuncSetAttribute(tc_gemm, cudaFuncAttributeMaxDynamicSharedMemorySize, SM_GEMM);
        smem_set = 1;
    }

    float *h, *qkv, *va, *vb, *ka, *kb, *scal, *kvm, *ksum;
    int *deg, *cursor;
    cudaGetSymbolAddress((void**)&h,    g_h);
    cudaGetSymbolAddress((void**)&qkv,  g_qkv);
    cudaGetSymbolAddress((void**)&va,   g_va);
    cudaGetSymbolAddress((void**)&vb,   g_vb);
    cudaGetSymbolAddress((void**)&ka,   g_ka);
    cudaGetSymbolAddress((void**)&kb,   g_kb);
    cudaGetSymbolAddress((void**)&scal, g_scal);
    cudaGetSymbolAddress((void**)&kvm,  g_kvm);
    cudaGetSymbolAddress((void**)&ksum, g_ksum);
    cudaGetSymbolAddress((void**)&deg,    g_deg);
    cudaGetSymbolAddress((void**)&cursor, g_cursor);
    __nv_bfloat16 *hnh, *hnl, *ah, *al, *vbh, *vbl, *kth, *ktl, *vth, *vtl, *kvth, *kvtl;
    __nv_bfloat16 *wgqh, *wgql, *waqh, *waql, *wgoh, *wgol, *waoh, *waol;
    cudaGetSymbolAddress((void**)&hnh, g_hn_hi); cudaGetSymbolAddress((void**)&hnl, g_hn_lo);
    cudaGetSymbolAddress((void**)&ah,  g_a_hi);  cudaGetSymbolAddress((void**)&al,  g_a_lo);
    cudaGetSymbolAddress((void**)&vbh, g_vbh);   cudaGetSymbolAddress((void**)&vbl, g_vbl);
    cudaGetSymbolAddress((void**)&kth, g_kT_hi); cudaGetSymbolAddress((void**)&ktl, g_kT_lo);
    cudaGetSymbolAddress((void**)&vth, g_vT_hi); cudaGetSymbolAddress((void**)&vtl, g_vT_lo);
    cudaGetSymbolAddress((void**)&kvth, g_kvT_hi); cudaGetSymbolAddress((void**)&kvtl, g_kvT_lo);
    cudaGetSymbolAddress((void**)&wgqh, g_wgq_hi); cudaGetSymbolAddress((void**)&wgql, g_wgq_lo);
    cudaGetSymbolAddress((void**)&waqh, g_waq_hi); cudaGetSymbolAddress((void**)&waql, g_waq_lo);
    cudaGetSymbolAddress((void**)&wgoh, g_wgo_hi); cudaGetSymbolAddress((void**)&wgol, g_wgo_lo);
    cudaGetSymbolAddress((void**)&waoh, g_wao_hi); cudaGetSymbolAddress((void**)&waol, g_wao_lo);

    const float s_hop = 1.0f / ((float)Kk + 1e-6f);
    const int egrid = BN * Kk / 256;

    // ---- front-loaded so tc_gemm is launch #4 (ncu capture target) ----
    tsplit<<<dim3(24, 8, Ll), 256>>>(grf_qkv, QLD, (long)Dd * QLD, wgqh, wgql, Dd, (long)QLD * Dd);
    embed_kernel<<<BN, Dd>>>(x, emb_w, emb_b);
    ln_kernel<<<BN, Dd>>>(norm_g, norm_b);
    tc_gemm<<<dim3(512, 6, 1), 256, SM_GEMM>>>(
        hnh, hnl, Dd, 0, wgqh, wgql, Dd, 0,
        1, 8, qkv, QLD, 0, nullptr, nullptr, nullptr, nullptr, 0, 0, 0, 1);

    // ---- CSR build (needed before first gather) ----
    zero_kernel<<<BN / 1024, 256>>>((float4*)deg, BN / 4);
    zero_kernel<<<BN / 1024, 256>>>((float4*)cursor, BN / 4);
    count_kernel<<<egrid, 256>>>(knn);
    scan1<<<64, 1024>>>();
    scan2<<<1, 1>>>();
    scan3<<<64, 1024>>>();
    fill_kernel<<<egrid, 256>>>(knn);

    // ---- remaining weight transpose + split ----
    tsplit<<<dim3(24, 8, Ll), 256>>>(attn_qkv, QLD, (long)Dd * QLD, waqh, waql, Dd, (long)QLD * Dd);
    tsplit<<<dim3(8, 8, Ll), 256>>>(grf_outw, Dd, (long)Dd * Dd, wgoh, wgol, Dd, (long)Dd * Dd);
    tsplit<<<dim3(8, 8, Ll), 256>>>(attn_outw, Dd, (long)Dd * Dd, waoh, waol, Dd, (long)Dd * Dd);

    for (int i = 0; i < Ll; i++) {
        // ===== GRF block =====
        if (i > 0) {
            ln_kernel<<<BN, Dd>>>(norm_g + (size_t)(2 * i) * Dd, norm_b + (size_t)(2 * i) * Dd);
            tc_gemm<<<dim3(512, 6, 1), 256, SM_GEMM>>>(
                hnh, hnl, Dd, 0, wgqh + (size_t)i * QLD * Dd, wgql + (size_t)i * QLD * Dd, Dd, 0,
                1, 8, qkv, QLD, 0, nullptr, nullptr, nullptr, nullptr, 0, 0, 0, 1);
        }
        gather2<<<dim3(BN, 2), 32>>>(qkv + 2 * Dd, qkv + Dd, QLD, s_hop, va, ka);
        gather2<<<dim3(BN, 2), 32>>>(va, ka, Dd, s_hop, vb, kb);
        gather_attnsplit<<<BN, 64>>>(vb, kb, s_hop);
        tc_gemm<<<dim3(512, 2, 1), 256, SM_GEMM>>>(
            ah, al, Dd, 0, wgoh + (size_t)i * Dd * Dd, wgol + (size_t)i * Dd * Dd, Dd, 0,
            1, 8, h, Dd, 0, grf_outb + (size_t)i * Dd, nullptr, nullptr, nullptr, 0, 0, 0, 2);

        // ===== linear attention block =====
        ln_kernel<<<BN, Dd>>>(norm_g + (size_t)(2 * i + 1) * Dd, norm_b + (size_t)(2 * i + 1) * Dd);
        // qkv: k,v fp32 only (cols >= 256); q emitted solely as bf16 split into ah/al
        tc_gemm<<<dim3(512, 6, 1), 256, SM_GEMM>>>(
            hnh, hnl, Dd, 0, waqh + (size_t)i * QLD * Dd, waql + (size_t)i * QLD * Dd, Dd, 0,
            1, 8, qkv, QLD, 0, nullptr, nullptr, ah, al, Dd, 2 * Dd, Dd, 16 | 8);
        zero_kernel<<<2, 256>>>((float4*)ksum, (long)Bc * Dd / 4);
        ksum_kernel<<<Bc * 128, 256>>>();
        tsplit<<<dim3(8, 256, Bc), 256>>>(qkv + Dd, QLD, (long)Nn * QLD, kth, ktl, Nn, (long)Dd * Nn);
        tsplit<<<dim3(8, 256, Bc), 256>>>(qkv + 2 * Dd, QLD, (long)Nn * QLD, vth, vtl, Nn, (long)Dd * Nn);
        zero_kernel<<<(Bc * Dd * Dd / 4 + 255) / 256, 256>>>((float4*)kvm, (long)Bc * Dd * Dd / 4);
        tc_gemm<<<dim3(2, 2, Bc * 16), 256, SM_GEMM>>>(
            kth, ktl, Nn, Dd, vth, vtl, Nn, Dd,
            16, 16, kvm, Dd, Dd, nullptr, nullptr, nullptr, nullptr, 0, 0, 0, 4);
        zcalc_kernel<<<BN * 32 / 256, 256>>>();
        tsplit<<<dim3(8, 8, Bc), 256>>>(kvm, Dd, (long)Dd * Dd, kvth, kvtl, Dd, (long)Dd * Dd);
        tc_gemm<<<dim3(64, 2, Bc), 256, SM_GEMM>>>(
            ah, al, Dd, Nn, kvth, kvtl, Dd, Dd,
            1, 8, nullptr, 0, Nn, nullptr, scal, vbh, vbl, Dd, 0, Dd, 8);
        tc_gemm<<<dim3(512, 2, 1), 256, SM_GEMM>>>(
            vbh, vbl, Dd, 0, waoh + (size_t)i * Dd * Dd, waol + (size_t)i * Dd * Dd, Dd, 0,
            1, 8, h, Dd, 0, attn_outb + (size_t)i * Dd, nullptr, nullptr, nullptr, 0, 0, 0, 2);
    }

    head_kernel<<<BN * 32 / 256, 256>>>(head_w, head_b, out);
}

// round 15
// speedup vs baseline: 1.1754x; 1.0066x over previous
#include <cuda_runtime.h>
#include <cuda_bf16.h>
#include <cstdint>

#define Bc 8
#define Nn 8192
#define Kk 6
#define Dd 256
#define Ll 5
#define BN 65536
#define QLD 768

// ===================== device scratch =====================
__device__ float g_h  [(size_t)BN * Dd];
__device__ float g_qkv[(size_t)BN * 3 * Dd];
__device__ float g_va [(size_t)BN * Dd];
__device__ float g_vb [(size_t)BN * Dd];
__device__ float g_ka [(size_t)BN * Dd];
__device__ float g_kb [(size_t)BN * Dd];
__device__ float g_scal[BN];
__device__ float g_kvm [Bc * Dd * Dd];
__device__ float g_ksum[Bc * Dd];

// CSR (transposed adjacency)
__device__ int g_deg[BN];
__device__ int g_cursor[BN];
__device__ int g_rowstart[BN + 1];
__device__ int g_csr_src[BN * Kk];
__device__ int g_part[64];
__device__ int g_partoff[64];

__device__ __align__(128) __nv_bfloat16 g_hn_hi[(size_t)BN * Dd], g_hn_lo[(size_t)BN * Dd];
__device__ __align__(128) __nv_bfloat16 g_a_hi [(size_t)BN * Dd], g_a_lo [(size_t)BN * Dd];
__device__ __align__(128) __nv_bfloat16 g_vbh  [(size_t)BN * Dd], g_vbl  [(size_t)BN * Dd];
__device__ __align__(128) __nv_bfloat16 g_kT_hi[(size_t)Bc * Dd * Nn], g_kT_lo[(size_t)Bc * Dd * Nn];
__device__ __align__(128) __nv_bfloat16 g_vT_hi[(size_t)Bc * Dd * Nn], g_vT_lo[(size_t)Bc * Dd * Nn];
__device__ __align__(128) __nv_bfloat16 g_kvT_hi[Bc * Dd * Dd], g_kvT_lo[Bc * Dd * Dd];
__device__ __align__(128) __nv_bfloat16 g_wgq_hi[Ll * 3 * Dd * Dd], g_wgq_lo[Ll * 3 * Dd * Dd];
__device__ __align__(128) __nv_bfloat16 g_waq_hi[Ll * 3 * Dd * Dd], g_waq_lo[Ll * 3 * Dd * Dd];
__device__ __align__(128) __nv_bfloat16 g_wgo_hi[Ll * Dd * Dd],     g_wgo_lo[Ll * Dd * Dd];
__device__ __align__(128) __nv_bfloat16 g_wao_hi[Ll * Dd * Dd],     g_wao_lo[Ll * Dd * Dd];

// ===================== PTX helpers (base PTX, sm_103-legal) ============
__device__ __forceinline__ uint32_t smem_to_u32(const void* p) {
    uint32_t a;
    asm("{ .reg .u64 t; cvta.to.shared.u64 t, %1; cvt.u32.u64 %0, t; }" : "=r"(a) : "l"(p));
    return a;
}
#define LDSM_X4(r0, r1, r2, r3, addr) \
    asm volatile("ldmatrix.sync.aligned.m8n8.x4.shared.b16 {%0,%1,%2,%3}, [%4];" \
        : "=r"(r0), "=r"(r1), "=r"(r2), "=r"(r3) : "r"(addr))
#define MMA_BF16(d, a, b) \
    asm volatile("mma.sync.aligned.m16n8k16.row.col.f32.bf16.bf16.f32 " \
        "{%0,%1,%2,%3}, {%4,%5,%6,%7}, {%8,%9}, {%0,%1,%2,%3};" \
        : "+f"((d)[0]), "+f"((d)[1]), "+f"((d)[2]), "+f"((d)[3]) \
        : "r"((a)[0]), "r"((a)[1]), "r"((a)[2]), "r"((a)[3]), "r"((b)[0]), "r"((b)[1]))
#define CP_ASYNC16(s, g) \
    asm volatile("cp.async.cg.shared.global [%0], [%1], 16;" :: "r"(s), "l"(g))
#define CP_COMMIT() asm volatile("cp.async.commit_group;" ::: "memory")
#define CP_WAIT0()  asm volatile("cp.async.wait_group 0;" ::: "memory")

__device__ __forceinline__ void split2(float v, __nv_bfloat16& hi, __nv_bfloat16& lo) {
    hi = __float2bfloat16(v);
    lo = __float2bfloat16(v - __bfloat162float(hi));
}

// ===================== tensor-core GEMM (FROZEN config) ==============
// 8 warps, CTA tile 128x128, warp tile 64x32, split-bf16 3-term.
// flags: 1 store fp32, 2 add fp32, 4 atomicAdd fp32, 8 store bf16-split (n<bf16Limit),
//        16 store fp32 only for n>=bf16Limit
#define STG 40960
#define SM_GEMM 81920

__global__ __launch_bounds__(256, 2) void tc_gemm(
    const __nv_bfloat16* __restrict__ Ah, const __nv_bfloat16* __restrict__ Al, int lda, int aBatchRows,
    const __nv_bfloat16* __restrict__ Bh, const __nv_bfloat16* __restrict__ Bl, int ldb, int bBatchRows,
    int nsplit, int kChunks,
    float* __restrict__ C, int ldc, int cBatchRows,
    const float* __restrict__ bias, const float* __restrict__ rowscale,
    __nv_bfloat16* __restrict__ Oh, __nv_bfloat16* __restrict__ Ol, int ldo,
    int reluLimit, int bf16Limit, int flags)
{
    extern __shared__ char dsm[];
    uint32_t sb = smem_to_u32(dsm);
    int t = threadIdx.x, wid = t >> 5, lane = t & 31;
    int batch = blockIdx.z / nsplit, ks = blockIdx.z % nsplit;
    int m0 = blockIdx.x * 128, n0 = blockIdx.y * 128;
    int kBase = ks * kChunks * 32;
    long aRow0 = (long)batch * aBatchRows + m0;
    long bRow0 = (long)batch * bBatchRows + n0;
    int wm = (wid & 1) * 64;
    int wn = (wid >> 1) * 32;

    float acc[4][4][4];
#pragma unroll
    for (int i = 0; i < 4; i++)
#pragma unroll
        for (int j = 0; j < 4; j++)
#pragma unroll
            for (int r = 0; r < 4; r++) acc[i][j][r] = 0.f;

    int lr = t >> 2, seg = t & 3;

#define LOAD_STAGE(c, st) do { \
        int kb = kBase + (c) * 32; \
        uint32_t sbase = sb + (st) * STG; \
        _Pragma("unroll") \
        for (int rr = 0; rr < 2; ++rr) { \
            int row = lr + rr * 64; \
            long ao = (aRow0 + row) * (long)lda + kb + seg * 8; \
            long bo = (bRow0 + row) * (long)ldb + kb + seg * 8; \
            uint32_t so = (uint32_t)row * 80 + seg * 16; \
            CP_ASYNC16(sbase + so,         (const char*)(Ah + ao)); \
            CP_ASYNC16(sbase + 10240 + so, (const char*)(Al + ao)); \
            CP_ASYNC16(sbase + 20480 + so, (const char*)(Bh + bo)); \
            CP_ASYNC16(sbase + 30720 + so, (const char*)(Bl + bo)); \
        } \
        CP_COMMIT(); \
    } while (0)

    LOAD_STAGE(0, 0);

    for (int c = 0; c < kChunks; ++c) {
        int st = c & 1;
        CP_WAIT0();
        __syncthreads();
        if (c + 1 < kChunks) LOAD_STAGE(c + 1, (c + 1) & 1);

        uint32_t uAh = sb + st * STG, uAl = uAh + 10240;
        uint32_t uBh = uAh + 20480,   uBl = uAh + 30720;
#pragma unroll
        for (int kk = 0; kk < 2; ++kk) {
            int kbb = kk * 16;
            uint32_t ah[4][4], al[4][4], bh[4][2], bl[4][2];
            int arow = (lane & 7) + ((lane >> 3) & 1) * 8;
            int acol = kbb + (lane >> 4) * 8;
#pragma unroll
            for (int mt = 0; mt < 4; ++mt) {
                uint32_t off = (uint32_t)(wm + mt * 16 + arow) * 80 + acol * 2;
                LDSM_X4(ah[mt][0], ah[mt][1], ah[mt][2], ah[mt][3], uAh + off);
                LDSM_X4(al[mt][0], al[mt][1], al[mt][2], al[mt][3], uAl + off);
            }
            int brow = (lane & 7) + ((lane >> 4) & 1) * 8;
            int bcol = kbb + ((lane >> 3) & 1) * 8;
#pragma unroll
            for (int p = 0; p < 2; ++p) {
                uint32_t off = (uint32_t)(wn + p * 16 + brow) * 80 + bcol * 2;
                LDSM_X4(bh[2 * p][0], bh[2 * p][1], bh[2 * p + 1][0], bh[2 * p + 1][1], uBh + off);
                LDSM_X4(bl[2 * p][0], bl[2 * p][1], bl[2 * p + 1][0], bl[2 * p + 1][1], uBl + off);
            }
#pragma unroll
            for (int mt = 0; mt < 4; ++mt)
#pragma unroll
                for (int nt = 0; nt < 4; ++nt) {
                    MMA_BF16(acc[mt][nt], ah[mt], bh[nt]);
                    MMA_BF16(acc[mt][nt], ah[mt], bl[nt]);
                    MMA_BF16(acc[mt][nt], al[mt], bh[nt]);
                }
        }
    }

    // epilogue
#pragma unroll
    for (int mt = 0; mt < 4; ++mt) {
        int r0g = m0 + wm + mt * 16 + (lane >> 2);
        long row0 = (long)batch * cBatchRows + r0g;
        long row1 = row0 + 8;
        float rs0 = rowscale ? rowscale[row0] : 1.f;
        float rs1 = rowscale ? rowscale[row1] : 1.f;
#pragma unroll
        for (int nt = 0; nt < 4; ++nt) {
            int c0 = n0 + wn + nt * 8 + (lane & 3) * 2;
#pragma unroll
            for (int half = 0; half < 2; ++half) {
                long row = half ? row1 : row0;
                float rs = half ? rs1 : rs0;
#pragma unroll
                for (int cc = 0; cc < 2; ++cc) {
                    float v = acc[mt][nt][half * 2 + cc] * rs;
                    int n = c0 + cc;
                    if (n < reluLimit) v = fmaxf(v, 0.f) + 1e-6f;
                    if (bias) v += bias[n];
                    if (flags & 1) C[row * ldc + n] = v;
                    if (flags & 2) C[row * ldc + n] += v;
                    if (flags & 4) atomicAdd(&C[row * ldc + n], v);
                    if ((flags & 16) && n >= bf16Limit) C[row * ldc + n] = v;
                    if ((flags & 8) && n < bf16Limit) {
                        __nv_bfloat16 hi, lo;
                        split2(v, hi, lo);
                        Oh[row * ldo + n] = hi;
                        Ol[row * ldo + n] = lo;
                    }
                }
            }
        }
    }
}

// ===================== SIMT kernels =====================
__device__ __forceinline__ float warp_sum(float v) {
#pragma unroll
    for (int o = 16; o > 0; o >>= 1) v += __shfl_xor_sync(0xffffffffu, v, o);
    return v;
}

__global__ void embed_kernel(const float* __restrict__ x, const float* __restrict__ w,
                             const float* __restrict__ b) {
    int row = blockIdx.x, t = threadIdx.x;
    float x0 = x[row * 3], x1 = x[row * 3 + 1], x2 = x[row * 3 + 2];
    g_h[(size_t)row * Dd + t] = b[t] + x0 * w[t] + x1 * w[Dd + t] + x2 * w[2 * Dd + t];
}

__global__ void ln_kernel(const float* __restrict__ g, const float* __restrict__ b) {
    int row = blockIdx.x, t = threadIdx.x;
    float x = g_h[(size_t)row * Dd + t];
    float s = warp_sum(x), s2 = warp_sum(x * x);
    __shared__ float sh1[8], sh2[8];
    int w = t >> 5, l = t & 31;
    if (l == 0) { sh1[w] = s; sh2[w] = s2; }
    __syncthreads();
    if (t == 0) {
        float a = 0.f, c = 0.f;
#pragma unroll
        for (int i = 0; i < 8; i++) { a += sh1[i]; c += sh2[i]; }
        sh1[0] = a; sh2[0] = c;
    }
    __syncthreads();
    float m = sh1[0] * (1.0f / Dd);
    float var = fmaxf(sh2[0] * (1.0f / Dd) - m * m, 0.0f);
    float inv = rsqrtf(var + 1e-5f);
    float y = (x - m) * inv * g[t] + b[t];
    __nv_bfloat16 hi, lo;
    split2(y, hi, lo);
    g_hn_hi[(size_t)row * Dd + t] = hi;
    g_hn_lo[(size_t)row * Dd + t] = lo;
}

__global__ void tsplit(const float* __restrict__ in, int ldi, long inB,
                       __nv_bfloat16* __restrict__ oh, __nv_bfloat16* __restrict__ ol,
                       int ldo, long oB) {
    int z = blockIdx.z;
    in += (long)z * inB; oh += (long)z * oB; ol += (long)z * oB;
    __shared__ float tb[32][33];
    int c0 = blockIdx.x * 32, r0 = blockIdx.y * 32;
    int tx = threadIdx.x & 31, ty = threadIdx.x >> 5;
#pragma unroll
    for (int i = 0; i < 4; ++i) {
        int r = ty + i * 8;
        tb[r][tx] = in[(long)(r0 + r) * ldi + c0 + tx];
    }
    __syncthreads();
#pragma unroll
    for (int i = 0; i < 4; ++i) {
        int c = ty + i * 8;
        float v = tb[tx][c];
        __nv_bfloat16 hi, lo;
        split2(v, hi, lo);
        oh[(long)(c0 + c) * ldo + r0 + tx] = hi;
        ol[(long)(c0 + c) * ldo + r0 + tx] = lo;
    }
}

// FUSED: transpose+split k AND v from qkv, plus ksum partial reduction of k.
// grid (8, 256, Bc), block 256. Tile 32x32.
__global__ void tsplit2_kv(__nv_bfloat16* __restrict__ kth, __nv_bfloat16* __restrict__ ktl,
                           __nv_bfloat16* __restrict__ vth, __nv_bfloat16* __restrict__ vtl) {
    int z = blockIdx.z;
    int c0 = blockIdx.x * 32, r0 = blockIdx.y * 32;
    const float* base = g_qkv + ((size_t)z * Nn + r0) * QLD;
    __shared__ float tk[32][33], tv[32][33];
    __shared__ float csum[32];
    int tx = threadIdx.x & 31, ty = threadIdx.x >> 5;
    if (threadIdx.x < 32) csum[threadIdx.x] = 0.f;
    float part = 0.f;
#pragma unroll
    for (int i = 0; i < 4; ++i) {
        int r = ty + i * 8;
        float kv_ = base[(size_t)r * QLD + Dd + c0 + tx];
        tk[r][tx] = kv_;
        part += kv_;
        tv[r][tx] = base[(size_t)r * QLD + 2 * Dd + c0 + tx];
    }
    __syncthreads();
    atomicAdd(&csum[tx], part);
    size_t ob = ((size_t)z * Dd) * Nn;
#pragma unroll
    for (int i = 0; i < 4; ++i) {
        int c = ty + i * 8;
        __nv_bfloat16 hi, lo;
        split2(tk[tx][c], hi, lo);
        kth[ob + (size_t)(c0 + c) * Nn + r0 + tx] = hi;
        ktl[ob + (size_t)(c0 + c) * Nn + r0 + tx] = lo;
        split2(tv[tx][c], hi, lo);
        vth[ob + (size_t)(c0 + c) * Nn + r0 + tx] = hi;
        vtl[ob + (size_t)(c0 + c) * Nn + r0 + tx] = lo;
    }
    __syncthreads();
    if (threadIdx.x < 32)
        atomicAdd(&g_ksum[z * Dd + c0 + threadIdx.x], csum[threadIdx.x]);
}

__global__ void zero_kernel(float4* __restrict__ p, long n4) {
    long i = (long)blockIdx.x * 256 + threadIdx.x;
    if (i < n4) p[i] = make_float4(0.f, 0.f, 0.f, 0.f);
}

// ---------- CSR build ----------
__global__ void count_kernel(const int* __restrict__ knn) {
    int e = blockIdx.x * 256 + threadIdx.x;
    int srow = e / Kk;
    int b = srow >> 13;
    atomicAdd(&g_deg[(b << 13) + knn[e]], 1);
}

__global__ void scan1() {
    int b = blockIdx.x, t = threadIdx.x;
    int v = g_deg[b * 1024 + t];
    v = (int)warp_sum((float)v);
    __shared__ int sh[32];
    if ((t & 31) == 0) sh[t >> 5] = v;
    __syncthreads();
    if (t == 0) {
        int s = 0;
#pragma unroll
        for (int i = 0; i < 32; i++) s += sh[i];
        g_part[b] = s;
    }
}
__global__ void scan2() {
    int run = 0;
    for (int i = 0; i < 64; i++) { g_partoff[i] = run; run += g_part[i]; }
}
__global__ void scan3() {
    __shared__ int sh[1024];
    int b = blockIdx.x, t = threadIdx.x;
    int v = g_deg[b * 1024 + t];
    sh[t] = v;
    __syncthreads();
#pragma unroll
    for (int off = 1; off < 1024; off <<= 1) {
        int x = (t >= off) ? sh[t - off] : 0;
        __syncthreads();
        sh[t] += x;
        __syncthreads();
    }
    int incl = sh[t];
    g_rowstart[b * 1024 + t] = g_partoff[b] + incl - v;
    if (b == 63 && t == 1023) g_rowstart[BN] = g_partoff[b] + incl;
}

__global__ void fill_kernel(const int* __restrict__ knn) {
    int e = blockIdx.x * 256 + threadIdx.x;
    int srow = e / Kk;
    int b = srow >> 13;
    int dst = (b << 13) + knn[e];
    int pos = g_rowstart[dst] + atomicAdd(&g_cursor[dst], 1);
    g_csr_src[pos] = srow;
}

// ---------- fused k/v gather hop: float4 loads, column-chunked ----------
__global__ void gather2(const float* __restrict__ s1, const float* __restrict__ s2, int sld,
                        float scale, float* __restrict__ d1, float* __restrict__ d2) {
    int j = blockIdx.x;
    int t4 = (blockIdx.y << 5) + threadIdx.x;
    int s = g_rowstart[j], e = g_rowstart[j + 1];
    float4 a1 = make_float4(0.f, 0.f, 0.f, 0.f);
    float4 a2 = make_float4(0.f, 0.f, 0.f, 0.f);
    for (int p = s; p < e; ++p) {
        long n = g_csr_src[p];
        float4 v1 = *(const float4*)(s1 + n * sld + (t4 << 2));
        float4 v2 = *(const float4*)(s2 + n * sld + (t4 << 2));
        a1.x += v1.x; a1.y += v1.y; a1.z += v1.z; a1.w += v1.w;
        a2.x += v2.x; a2.y += v2.y; a2.z += v2.z; a2.w += v2.w;
    }
    a1.x *= scale; a1.y *= scale; a1.z *= scale; a1.w *= scale;
    a2.x *= scale; a2.y *= scale; a2.z *= scale; a2.w *= scale;
    *(float4*)(d1 + (long)j * Dd + (t4 << 2)) = a1;
    *(float4*)(d2 + (long)j * Dd + (t4 << 2)) = a2;
}

// ---------- FUSED hop-3 gather + attn scalar + split (float4, block 64) ----------
__global__ void gather_attnsplit(const float* __restrict__ vb, const float* __restrict__ kb,
                                 float scale) {
    int row = blockIdx.x, t4 = threadIdx.x;
    int s = g_rowstart[row], e = g_rowstart[row + 1];
    float4 av = make_float4(0.f, 0.f, 0.f, 0.f);
    float4 ak = make_float4(0.f, 0.f, 0.f, 0.f);
    for (int p = s; p < e; ++p) {
        long n = g_csr_src[p];
        float4 v = *(const float4*)(vb + n * Dd + (t4 << 2));
        float4 k = *(const float4*)(kb + n * Dd + (t4 << 2));
        av.x += v.x; av.y += v.y; av.z += v.z; av.w += v.w;
        ak.x += k.x; ak.y += k.y; ak.z += k.z; ak.w += k.w;
    }
    av.x *= scale; av.y *= scale; av.z *= scale; av.w *= scale;
    ak.x *= scale; ak.y *= scale; ak.z *= scale; ak.w *= scale;
    float4 q = *(const float4*)(&g_qkv[(size_t)row * QLD + (t4 << 2)]);
    float pr = q.x * ak.x + q.y * ak.y + q.z * ak.z + q.w * ak.w;
    pr = warp_sum(pr);
    __shared__ float sh[2];
    int w = t4 >> 5, l = t4 & 31;
    if (l == 0) sh[w] = pr;
    __syncthreads();
    float sdot = sh[0] + sh[1];
    float vv[4] = {av.x * sdot, av.y * sdot, av.z * sdot, av.w * sdot};
    size_t base = (size_t)row * Dd + (t4 << 2);
#pragma unroll
    for (int i = 0; i < 4; ++i) {
        __nv_bfloat16 hi, lo;
        split2(vv[i], hi, lo);
        g_a_hi[base + i] = hi;
        g_a_lo[base + i] = lo;
    }
}

// z from bf16-split q
__global__ void zcalc_kernel() {
    long gt = (long)blockIdx.x * 256 + threadIdx.x;
    int row = (int)(gt >> 5), lane = (int)(gt & 31);
    int b = row >> 13;
    float s = 0.f;
#pragma unroll
    for (int it = 0; it < 8; it++) {
        int d = it * 32 + lane;
        float q = __bfloat162float(g_a_hi[(size_t)row * Dd + d]) +
                  __bfloat162float(g_a_lo[(size_t)row * Dd + d]);
        s += q * g_ksum[b * Dd + d];
    }
    s = warp_sum(s);
    if (lane == 0) g_scal[row] = 1.0f / (s + 1e-6f);
}

__global__ void head_kernel(const float* __restrict__ w, const float* __restrict__ hb,
                            float* __restrict__ out) {
    long gt = (long)blockIdx.x * 256 + threadIdx.x;
    int row = (int)(gt >> 5), lane = (int)(gt & 31);
    float a0 = 0.f, a1 = 0.f, a2 = 0.f;
#pragma unroll
    for (int it = 0; it < 8; it++) {
        int d = it * 32 + lane;
        float hv = g_h[(size_t)row * Dd + d];
        a0 += hv * w[d * 3 + 0];
        a1 += hv * w[d * 3 + 1];
        a2 += hv * w[d * 3 + 2];
    }
    a0 = warp_sum(a0); a1 = warp_sum(a1); a2 = warp_sum(a2);
    if (lane == 0) {
        out[(size_t)row * 3 + 0] = a0 + hb[0];
        out[(size_t)row * 3 + 1] = a1 + hb[1];
        out[(size_t)row * 3 + 2] = a2 + hb[2];
    }
}

// ===================== host =====================
extern "C" void kernel_launch(void* const* d_in, const int* in_sizes, int n_in,
                              void* d_out, int out_size) {
    const float* x        = (const float*)d_in[0];
    const int*   knn      = (const int*)  d_in[1];
    const float* emb_w    = (const float*)d_in[2];
    const float* emb_b    = (const float*)d_in[3];
    const float* norm_g   = (const float*)d_in[4];
    const float* norm_b   = (const float*)d_in[5];
    const float* grf_qkv  = (const float*)d_in[6];
    const float* grf_outw = (const float*)d_in[7];
    const float* grf_outb = (const float*)d_in[8];
    const float* attn_qkv = (const float*)d_in[9];
    const float* attn_outw= (const float*)d_in[10];
    const float* attn_outb= (const float*)d_in[11];
    const float* head_w   = (const float*)d_in[12];
    const float* head_b   = (const float*)d_in[13];
    float* out = (float*)d_out;

    static int smem_set = 0;
    if (!smem_set) {
        cudaFuncSetAttribute(tc_gemm, cudaFuncAttributeMaxDynamicSharedMemorySize, SM_GEMM);
        smem_set = 1;
    }

    float *h, *qkv, *va, *vb, *ka, *kb, *scal, *kvm, *ksum;
    int *deg, *cursor;
    cudaGetSymbolAddress((void**)&h,    g_h);
    cudaGetSymbolAddress((void**)&qkv,  g_qkv);
    cudaGetSymbolAddress((void**)&va,   g_va);
    cudaGetSymbolAddress((void**)&vb,   g_vb);
    cudaGetSymbolAddress((void**)&ka,   g_ka);
    cudaGetSymbolAddress((void**)&kb,   g_kb);
    cudaGetSymbolAddress((void**)&scal, g_scal);
    cudaGetSymbolAddress((void**)&kvm,  g_kvm);
    cudaGetSymbolAddress((void**)&ksum, g_ksum);
    cudaGetSymbolAddress((void**)&deg,    g_deg);
    cudaGetSymbolAddress((void**)&cursor, g_cursor);
    __nv_bfloat16 *hnh, *hnl, *ah, *al, *vbh, *vbl, *kth, *ktl, *vth, *vtl, *kvth, *kvtl;
    __nv_bfloat16 *wgqh, *wgql, *waqh, *waql, *wgoh, *wgol, *waoh, *waol;
    cudaGetSymbolAddress((void**)&hnh, g_hn_hi); cudaGetSymbolAddress((void**)&hnl, g_hn_lo);
    cudaGetSymbolAddress((void**)&ah,  g_a_hi);  cudaGetSymbolAddress((void**)&al,  g_a_lo);
    cudaGetSymbolAddress((void**)&vbh, g_vbh);   cudaGetSymbolAddress((void**)&vbl, g_vbl);
    cudaGetSymbolAddress((void**)&kth, g_kT_hi); cudaGetSymbolAddress((void**)&ktl, g_kT_lo);
    cudaGetSymbolAddress((void**)&vth, g_vT_hi); cudaGetSymbolAddress((void**)&vtl, g_vT_lo);
    cudaGetSymbolAddress((void**)&kvth, g_kvT_hi); cudaGetSymbolAddress((void**)&kvtl, g_kvT_lo);
    cudaGetSymbolAddress((void**)&wgqh, g_wgq_hi); cudaGetSymbolAddress((void**)&wgql, g_wgq_lo);
    cudaGetSymbolAddress((void**)&waqh, g_waq_hi); cudaGetSymbolAddress((void**)&waql, g_waq_lo);
    cudaGetSymbolAddress((void**)&wgoh, g_wgo_hi); cudaGetSymbolAddress((void**)&wgol, g_wgo_lo);
    cudaGetSymbolAddress((void**)&waoh, g_wao_hi); cudaGetSymbolAddress((void**)&waol, g_wao_lo);

    const float s_hop = 1.0f / ((float)Kk + 1e-6f);
    const int egrid = BN * Kk / 256;

    // ---- front-loaded so tc_gemm is launch #4 (ncu capture target) ----
    tsplit<<<dim3(24, 8, Ll), 256>>>(grf_qkv, QLD, (long)Dd * QLD, wgqh, wgql, Dd, (long)QLD * Dd);
    embed_kernel<<<BN, Dd>>>(x, emb_w, emb_b);
    ln_kernel<<<BN, Dd>>>(norm_g, norm_b);
    tc_gemm<<<dim3(512, 6, 1), 256, SM_GEMM>>>(
        hnh, hnl, Dd, 0, wgqh, wgql, Dd, 0,
        1, 8, qkv, QLD, 0, nullptr, nullptr, nullptr, nullptr, 0, 0, 0, 1);

    // ---- CSR build (needed before first gather) ----
    zero_kernel<<<BN / 1024, 256>>>((float4*)deg, BN / 4);
    zero_kernel<<<BN / 1024, 256>>>((float4*)cursor, BN / 4);
    count_kernel<<<egrid, 256>>>(knn);
    scan1<<<64, 1024>>>();
    scan2<<<1, 1>>>();
    scan3<<<64, 1024>>>();
    fill_kernel<<<egrid, 256>>>(knn);

    // ---- remaining weight transpose + split ----
    tsplit<<<dim3(24, 8, Ll), 256>>>(attn_qkv, QLD, (long)Dd * QLD, waqh, waql, Dd, (long)QLD * Dd);
    tsplit<<<dim3(8, 8, Ll), 256>>>(grf_outw, Dd, (long)Dd * Dd, wgoh, wgol, Dd, (long)Dd * Dd);
    tsplit<<<dim3(8, 8, Ll), 256>>>(attn_outw, Dd, (long)Dd * Dd, waoh, waol, Dd, (long)Dd * Dd);

    for (int i = 0; i < Ll; i++) {
        // ===== GRF block =====
        if (i > 0) {
            ln_kernel<<<BN, Dd>>>(norm_g + (size_t)(2 * i) * Dd, norm_b + (size_t)(2 * i) * Dd);
            tc_gemm<<<dim3(512, 6, 1), 256, SM_GEMM>>>(
                hnh, hnl, Dd, 0, wgqh + (size_t)i * QLD * Dd, wgql + (size_t)i * QLD * Dd, Dd, 0,
                1, 8, qkv, QLD, 0, nullptr, nullptr, nullptr, nullptr, 0, 0, 0, 1);
        }
        gather2<<<dim3(BN, 2), 32>>>(qkv + 2 * Dd, qkv + Dd, QLD, s_hop, va, ka);
        gather2<<<dim3(BN, 2), 32>>>(va, ka, Dd, s_hop, vb, kb);
        gather_attnsplit<<<BN, 64>>>(vb, kb, s_hop);
        tc_gemm<<<dim3(512, 2, 1), 256, SM_GEMM>>>(
            ah, al, Dd, 0, wgoh + (size_t)i * Dd * Dd, wgol + (size_t)i * Dd * Dd, Dd, 0,
            1, 8, h, Dd, 0, grf_outb + (size_t)i * Dd, nullptr, nullptr, nullptr, 0, 0, 0, 2);

        // ===== linear attention block =====
        ln_kernel<<<BN, Dd>>>(norm_g + (size_t)(2 * i + 1) * Dd, norm_b + (size_t)(2 * i + 1) * Dd);
        // qkv: k,v fp32 (cols >= 256); q only as bf16 split into ah/al
        tc_gemm<<<dim3(512, 6, 1), 256, SM_GEMM>>>(
            hnh, hnl, Dd, 0, waqh + (size_t)i * QLD * Dd, waql + (size_t)i * QLD * Dd, Dd, 0,
            1, 8, qkv, QLD, 0, nullptr, nullptr, ah, al, Dd, 2 * Dd, Dd, 16 | 8);
        zero_kernel<<<2, 256>>>((float4*)ksum, (long)Bc * Dd / 4);
        // fused k/v transpose-split + ksum reduction
        tsplit2_kv<<<dim3(8, 256, Bc), 256>>>(kth, ktl, vth, vtl);
        zero_kernel<<<(Bc * Dd * Dd / 4 + 255) / 256, 256>>>((float4*)kvm, (long)Bc * Dd * Dd / 4);
        tc_gemm<<<dim3(2, 2, Bc * 16), 256, SM_GEMM>>>(
            kth, ktl, Nn, Dd, vth, vtl, Nn, Dd,
            16, 16, kvm, Dd, Dd, nullptr, nullptr, nullptr, nullptr, 0, 0, 0, 4);
        zcalc_kernel<<<BN * 32 / 256, 256>>>();
        tsplit<<<dim3(8, 8, Bc), 256>>>(kvm, Dd, (long)Dd * Dd, kvth, kvtl, Dd, (long)Dd * Dd);
        tc_gemm<<<dim3(64, 2, Bc), 256, SM_GEMM>>>(
            ah, al, Dd, Nn, kvth, kvtl, Dd, Dd,
            1, 8, nullptr, 0, Nn, nullptr, scal, vbh, vbl, Dd, 0, Dd, 8);
        tc_gemm<<<dim3(512, 2, 1), 256, SM_GEMM>>>(
            vbh, vbl, Dd, 0, waoh + (size_t)i * Dd * Dd, waol + (size_t)i * Dd * Dd, Dd, 0,
            1, 8, h, Dd, 0, attn_outb + (size_t)i * Dd, nullptr, nullptr, nullptr, 0, 0, 0, 2);
    }

    head_kernel<<<BN * 32 / 256, 256>>>(head_w, head_b, out);
}

// round 16
// speedup vs baseline: 1.2279x; 1.0446x over previous
#include <cuda_runtime.h>
#include <cuda_bf16.h>
#include <cstdint>

#define Bc 8
#define Nn 8192
#define Kk 6
#define Dd 256
#define Ll 5
#define BN 65536
#define QLD 768

// ===================== device scratch =====================
__device__ float g_h  [(size_t)BN * Dd];
__device__ float g_qkv[(size_t)BN * 3 * Dd];
__device__ float g_va [(size_t)BN * Dd];
__device__ float g_vb [(size_t)BN * Dd];
__device__ float g_ka [(size_t)BN * Dd];
__device__ float g_kb [(size_t)BN * Dd];
__device__ float g_scal[BN];
__device__ float g_kvm [Bc * Dd * Dd];
__device__ float g_ksum[Bc * Dd];

// CSR (transposed adjacency)
__device__ int g_deg[BN];
__device__ int g_cursor[BN];
__device__ int g_rowstart[BN + 1];
__device__ int g_csr_src[BN * Kk];
__device__ int g_part[64];
__device__ int g_partoff[64];

__device__ __align__(128) __nv_bfloat16 g_hn_hi[(size_t)BN * Dd], g_hn_lo[(size_t)BN * Dd];
__device__ __align__(128) __nv_bfloat16 g_a_hi [(size_t)BN * Dd], g_a_lo [(size_t)BN * Dd];
__device__ __align__(128) __nv_bfloat16 g_vbh  [(size_t)BN * Dd], g_vbl  [(size_t)BN * Dd];
__device__ __align__(128) __nv_bfloat16 g_kT_hi[(size_t)Bc * Dd * Nn], g_kT_lo[(size_t)Bc * Dd * Nn];
__device__ __align__(128) __nv_bfloat16 g_vT_hi[(size_t)Bc * Dd * Nn], g_vT_lo[(size_t)Bc * Dd * Nn];
__device__ __align__(128) __nv_bfloat16 g_kvT_hi[Bc * Dd * Dd], g_kvT_lo[Bc * Dd * Dd];
__device__ __align__(128) __nv_bfloat16 g_wgq_hi[Ll * 3 * Dd * Dd], g_wgq_lo[Ll * 3 * Dd * Dd];
__device__ __align__(128) __nv_bfloat16 g_waq_hi[Ll * 3 * Dd * Dd], g_waq_lo[Ll * 3 * Dd * Dd];
__device__ __align__(128) __nv_bfloat16 g_wgo_hi[Ll * Dd * Dd],     g_wgo_lo[Ll * Dd * Dd];
__device__ __align__(128) __nv_bfloat16 g_wao_hi[Ll * Dd * Dd],     g_wao_lo[Ll * Dd * Dd];

// ===================== PTX helpers (base PTX, sm_103-legal) ============
__device__ __forceinline__ uint32_t smem_to_u32(const void* p) {
    uint32_t a;
    asm("{ .reg .u64 t; cvta.to.shared.u64 t, %1; cvt.u32.u64 %0, t; }" : "=r"(a) : "l"(p));
    return a;
}
#define LDSM_X4(r0, r1, r2, r3, addr) \
    asm volatile("ldmatrix.sync.aligned.m8n8.x4.shared.b16 {%0,%1,%2,%3}, [%4];" \
        : "=r"(r0), "=r"(r1), "=r"(r2), "=r"(r3) : "r"(addr))
#define MMA_BF16(d, a, b) \
    asm volatile("mma.sync.aligned.m16n8k16.row.col.f32.bf16.bf16.f32 " \
        "{%0,%1,%2,%3}, {%4,%5,%6,%7}, {%8,%9}, {%0,%1,%2,%3};" \
        : "+f"((d)[0]), "+f"((d)[1]), "+f"((d)[2]), "+f"((d)[3]) \
        : "r"((a)[0]), "r"((a)[1]), "r"((a)[2]), "r"((a)[3]), "r"((b)[0]), "r"((b)[1]))
#define CP_ASYNC16(s, g) \
    asm volatile("cp.async.cg.shared.global [%0], [%1], 16;" :: "r"(s), "l"(g))
#define CP_COMMIT() asm volatile("cp.async.commit_group;" ::: "memory")
#define CP_WAIT0()  asm volatile("cp.async.wait_group 0;" ::: "memory")

__device__ __forceinline__ void split2(float v, __nv_bfloat16& hi, __nv_bfloat16& lo) {
    hi = __float2bfloat16(v);
    lo = __float2bfloat16(v - __bfloat162float(hi));
}

// ===================== tensor-core GEMM (FROZEN mainloop) ==============
// 8 warps, CTA tile 128x128, warp tile 64x32, split-bf16 3-term.
// GRID: x = N-tile, y = M-tile (same-A CTAs adjacent for L2 reuse).
// flags: 1 store fp32, 2 add fp32, 4 atomicAdd fp32, 8 store bf16-split (n<bf16Limit),
//        16 store fp32 only for n>=bf16Limit
#define STG 40960
#define SM_GEMM 81920

__global__ __launch_bounds__(256, 2) void tc_gemm(
    const __nv_bfloat16* __restrict__ Ah, const __nv_bfloat16* __restrict__ Al, int lda, int aBatchRows,
    const __nv_bfloat16* __restrict__ Bh, const __nv_bfloat16* __restrict__ Bl, int ldb, int bBatchRows,
    int nsplit, int kChunks,
    float* __restrict__ C, int ldc, int cBatchRows,
    const float* __restrict__ bias, const float* __restrict__ rowscale,
    __nv_bfloat16* __restrict__ Oh, __nv_bfloat16* __restrict__ Ol, int ldo,
    int reluLimit, int bf16Limit, int flags)
{
    extern __shared__ char dsm[];
    uint32_t sb = smem_to_u32(dsm);
    int t = threadIdx.x, wid = t >> 5, lane = t & 31;
    int batch = blockIdx.z / nsplit, ks = blockIdx.z % nsplit;
    int m0 = blockIdx.y * 128, n0 = blockIdx.x * 128;   // grid-transposed for A reuse
    int kBase = ks * kChunks * 32;
    long aRow0 = (long)batch * aBatchRows + m0;
    long bRow0 = (long)batch * bBatchRows + n0;
    int wm = (wid & 1) * 64;
    int wn = (wid >> 1) * 32;

    float acc[4][4][4];
#pragma unroll
    for (int i = 0; i < 4; i++)
#pragma unroll
        for (int j = 0; j < 4; j++)
#pragma unroll
            for (int r = 0; r < 4; r++) acc[i][j][r] = 0.f;

    int lr = t >> 2, seg = t & 3;

#define LOAD_STAGE(c, st) do { \
        int kb = kBase + (c) * 32; \
        uint32_t sbase = sb + (st) * STG; \
        _Pragma("unroll") \
        for (int rr = 0; rr < 2; ++rr) { \
            int row = lr + rr * 64; \
            long ao = (aRow0 + row) * (long)lda + kb + seg * 8; \
            long bo = (bRow0 + row) * (long)ldb + kb + seg * 8; \
            uint32_t so = (uint32_t)row * 80 + seg * 16; \
            CP_ASYNC16(sbase + so,         (const char*)(Ah + ao)); \
            CP_ASYNC16(sbase + 10240 + so, (const char*)(Al + ao)); \
            CP_ASYNC16(sbase + 20480 + so, (const char*)(Bh + bo)); \
            CP_ASYNC16(sbase + 30720 + so, (const char*)(Bl + bo)); \
        } \
        CP_COMMIT(); \
    } while (0)

    LOAD_STAGE(0, 0);

    for (int c = 0; c < kChunks; ++c) {
        int st = c & 1;
        CP_WAIT0();
        __syncthreads();
        if (c + 1 < kChunks) LOAD_STAGE(c + 1, (c + 1) & 1);

        uint32_t uAh = sb + st * STG, uAl = uAh + 10240;
        uint32_t uBh = uAh + 20480,   uBl = uAh + 30720;
#pragma unroll
        for (int kk = 0; kk < 2; ++kk) {
            int kbb = kk * 16;
            uint32_t ah[4][4], al[4][4], bh[4][2], bl[4][2];
            int arow = (lane & 7) + ((lane >> 3) & 1) * 8;
            int acol = kbb + (lane >> 4) * 8;
#pragma unroll
            for (int mt = 0; mt < 4; ++mt) {
                uint32_t off = (uint32_t)(wm + mt * 16 + arow) * 80 + acol * 2;
                LDSM_X4(ah[mt][0], ah[mt][1], ah[mt][2], ah[mt][3], uAh + off);
                LDSM_X4(al[mt][0], al[mt][1], al[mt][2], al[mt][3], uAl + off);
            }
            int brow = (lane & 7) + ((lane >> 4) & 1) * 8;
            int bcol = kbb + ((lane >> 3) & 1) * 8;
#pragma unroll
            for (int p = 0; p < 2; ++p) {
                uint32_t off = (uint32_t)(wn + p * 16 + brow) * 80 + bcol * 2;
                LDSM_X4(bh[2 * p][0], bh[2 * p][1], bh[2 * p + 1][0], bh[2 * p + 1][1], uBh + off);
                LDSM_X4(bl[2 * p][0], bl[2 * p][1], bl[2 * p + 1][0], bl[2 * p + 1][1], uBl + off);
            }
#pragma unroll
            for (int mt = 0; mt < 4; ++mt)
#pragma unroll
                for (int nt = 0; nt < 4; ++nt) {
                    MMA_BF16(acc[mt][nt], ah[mt], bh[nt]);
                    MMA_BF16(acc[mt][nt], ah[mt], bl[nt]);
                    MMA_BF16(acc[mt][nt], al[mt], bh[nt]);
                }
        }
    }

    // epilogue
#pragma unroll
    for (int mt = 0; mt < 4; ++mt) {
        int r0g = m0 + wm + mt * 16 + (lane >> 2);
        long row0 = (long)batch * cBatchRows + r0g;
        long row1 = row0 + 8;
        float rs0 = rowscale ? rowscale[row0] : 1.f;
        float rs1 = rowscale ? rowscale[row1] : 1.f;
#pragma unroll
        for (int nt = 0; nt < 4; ++nt) {
            int c0 = n0 + wn + nt * 8 + (lane & 3) * 2;
#pragma unroll
            for (int half = 0; half < 2; ++half) {
                long row = half ? row1 : row0;
                float rs = half ? rs1 : rs0;
#pragma unroll
                for (int cc = 0; cc < 2; ++cc) {
                    float v = acc[mt][nt][half * 2 + cc] * rs;
                    int n = c0 + cc;
                    if (n < reluLimit) v = fmaxf(v, 0.f) + 1e-6f;
                    if (bias) v += bias[n];
                    if (flags & 1) C[row * ldc + n] = v;
                    if (flags & 2) C[row * ldc + n] += v;
                    if (flags & 4) atomicAdd(&C[row * ldc + n], v);
                    if ((flags & 16) && n >= bf16Limit) C[row * ldc + n] = v;
                    if ((flags & 8) && n < bf16Limit) {
                        __nv_bfloat16 hi, lo;
                        split2(v, hi, lo);
                        Oh[row * ldo + n] = hi;
                        Ol[row * ldo + n] = lo;
                    }
                }
            }
        }
    }
}

// ===================== SIMT kernels =====================
__device__ __forceinline__ float warp_sum(float v) {
#pragma unroll
    for (int o = 16; o > 0; o >>= 1) v += __shfl_xor_sync(0xffffffffu, v, o);
    return v;
}

__global__ void embed_kernel(const float* __restrict__ x, const float* __restrict__ w,
                             const float* __restrict__ b) {
    int row = blockIdx.x, t = threadIdx.x;
    float x0 = x[row * 3], x1 = x[row * 3 + 1], x2 = x[row * 3 + 2];
    g_h[(size_t)row * Dd + t] = b[t] + x0 * w[t] + x1 * w[Dd + t] + x2 * w[2 * Dd + t];
}

__global__ void ln_kernel(const float* __restrict__ g, const float* __restrict__ b) {
    int row = blockIdx.x, t = threadIdx.x;
    float x = g_h[(size_t)row * Dd + t];
    float s = warp_sum(x), s2 = warp_sum(x * x);
    __shared__ float sh1[8], sh2[8];
    int w = t >> 5, l = t & 31;
    if (l == 0) { sh1[w] = s; sh2[w] = s2; }
    __syncthreads();
    if (t == 0) {
        float a = 0.f, c = 0.f;
#pragma unroll
        for (int i = 0; i < 8; i++) { a += sh1[i]; c += sh2[i]; }
        sh1[0] = a; sh2[0] = c;
    }
    __syncthreads();
    float m = sh1[0] * (1.0f / Dd);
    float var = fmaxf(sh2[0] * (1.0f / Dd) - m * m, 0.0f);
    float inv = rsqrtf(var + 1e-5f);
    float y = (x - m) * inv * g[t] + b[t];
    __nv_bfloat16 hi, lo;
    split2(y, hi, lo);
    g_hn_hi[(size_t)row * Dd + t] = hi;
    g_hn_lo[(size_t)row * Dd + t] = lo;
}

__global__ void tsplit(const float* __restrict__ in, int ldi, long inB,
                       __nv_bfloat16* __restrict__ oh, __nv_bfloat16* __restrict__ ol,
                       int ldo, long oB) {
    int z = blockIdx.z;
    in += (long)z * inB; oh += (long)z * oB; ol += (long)z * oB;
    __shared__ float tb[32][33];
    int c0 = blockIdx.x * 32, r0 = blockIdx.y * 32;
    int tx = threadIdx.x & 31, ty = threadIdx.x >> 5;
#pragma unroll
    for (int i = 0; i < 4; ++i) {
        int r = ty + i * 8;
        tb[r][tx] = in[(long)(r0 + r) * ldi + c0 + tx];
    }
    __syncthreads();
#pragma unroll
    for (int i = 0; i < 4; ++i) {
        int c = ty + i * 8;
        float v = tb[tx][c];
        __nv_bfloat16 hi, lo;
        split2(v, hi, lo);
        oh[(long)(c0 + c) * ldo + r0 + tx] = hi;
        ol[(long)(c0 + c) * ldo + r0 + tx] = lo;
    }
}

// FUSED: transpose+split k AND v from qkv, plus ksum partial reduction of k.
__global__ void tsplit2_kv(__nv_bfloat16* __restrict__ kth, __nv_bfloat16* __restrict__ ktl,
                           __nv_bfloat16* __restrict__ vth, __nv_bfloat16* __restrict__ vtl) {
    int z = blockIdx.z;
    int c0 = blockIdx.x * 32, r0 = blockIdx.y * 32;
    const float* base = g_qkv + ((size_t)z * Nn + r0) * QLD;
    __shared__ float tk[32][33], tv[32][33];
    __shared__ float csum[32];
    int tx = threadIdx.x & 31, ty = threadIdx.x >> 5;
    if (threadIdx.x < 32) csum[threadIdx.x] = 0.f;
    float part = 0.f;
#pragma unroll
    for (int i = 0; i < 4; ++i) {
        int r = ty + i * 8;
        float kv_ = base[(size_t)r * QLD + Dd + c0 + tx];
        tk[r][tx] = kv_;
        part += kv_;
        tv[r][tx] = base[(size_t)r * QLD + 2 * Dd + c0 + tx];
    }
    __syncthreads();
    atomicAdd(&csum[tx], part);
    size_t ob = ((size_t)z * Dd) * Nn;
#pragma unroll
    for (int i = 0; i < 4; ++i) {
        int c = ty + i * 8;
        __nv_bfloat16 hi, lo;
        split2(tk[tx][c], hi, lo);
        kth[ob + (size_t)(c0 + c) * Nn + r0 + tx] = hi;
        ktl[ob + (size_t)(c0 + c) * Nn + r0 + tx] = lo;
        split2(tv[tx][c], hi, lo);
        vth[ob + (size_t)(c0 + c) * Nn + r0 + tx] = hi;
        vtl[ob + (size_t)(c0 + c) * Nn + r0 + tx] = lo;
    }
    __syncthreads();
    if (threadIdx.x < 32)
        atomicAdd(&g_ksum[z * Dd + c0 + threadIdx.x], csum[threadIdx.x]);
}

__global__ void zero_kernel(float4* __restrict__ p, long n4) {
    long i = (long)blockIdx.x * 256 + threadIdx.x;
    if (i < n4) p[i] = make_float4(0.f, 0.f, 0.f, 0.f);
}

// zero two buffers in one launch (kvm float4 count n4a, then ksum n4b)
__global__ void zero2_kernel(float4* __restrict__ a, long n4a,
                             float4* __restrict__ b, long n4b) {
    long i = (long)blockIdx.x * 256 + threadIdx.x;
    if (i < n4a) a[i] = make_float4(0.f, 0.f, 0.f, 0.f);
    else if (i < n4a + n4b) b[i - n4a] = make_float4(0.f, 0.f, 0.f, 0.f);
}

// ---------- CSR build ----------
__global__ void count_kernel(const int* __restrict__ knn) {
    int e = blockIdx.x * 256 + threadIdx.x;
    int srow = e / Kk;
    int b = srow >> 13;
    atomicAdd(&g_deg[(b << 13) + knn[e]], 1);
}

__global__ void scan1() {
    int b = blockIdx.x, t = threadIdx.x;
    int v = g_deg[b * 1024 + t];
    v = (int)warp_sum((float)v);
    __shared__ int sh[32];
    if ((t & 31) == 0) sh[t >> 5] = v;
    __syncthreads();
    if (t == 0) {
        int s = 0;
#pragma unroll
        for (int i = 0; i < 32; i++) s += sh[i];
        g_part[b] = s;
    }
}
__global__ void scan2() {
    int run = 0;
    for (int i = 0; i < 64; i++) { g_partoff[i] = run; run += g_part[i]; }
}
__global__ void scan3() {
    __shared__ int sh[1024];
    int b = blockIdx.x, t = threadIdx.x;
    int v = g_deg[b * 1024 + t];
    sh[t] = v;
    __syncthreads();
#pragma unroll
    for (int off = 1; off < 1024; off <<= 1) {
        int x = (t >= off) ? sh[t - off] : 0;
        __syncthreads();
        sh[t] += x;
        __syncthreads();
    }
    int incl = sh[t];
    g_rowstart[b * 1024 + t] = g_partoff[b] + incl - v;
    if (b == 63 && t == 1023) g_rowstart[BN] = g_partoff[b] + incl;
}

__global__ void fill_kernel(const int* __restrict__ knn) {
    int e = blockIdx.x * 256 + threadIdx.x;
    int srow = e / Kk;
    int b = srow >> 13;
    int dst = (b << 13) + knn[e];
    int pos = g_rowstart[dst] + atomicAdd(&g_cursor[dst], 1);
    g_csr_src[pos] = srow;
}

// ---------- fused k/v gather hop: float4, 128-thread blocks (4 warps = 4 (row,chunk) units) ----------
// grid BN/2; warp w: row j = blockIdx.x*2 + (w>>1), chunk (w&1) covering 32 float4s.
__global__ void gather2(const float* __restrict__ s1, const float* __restrict__ s2, int sld,
                        float scale, float* __restrict__ d1, float* __restrict__ d2) {
    int w = threadIdx.x >> 5;
    int j = blockIdx.x * 2 + (w >> 1);
    int t4 = ((w & 1) << 5) + (threadIdx.x & 31);
    int s = g_rowstart[j], e = g_rowstart[j + 1];
    float4 a1 = make_float4(0.f, 0.f, 0.f, 0.f);
    float4 a2 = make_float4(0.f, 0.f, 0.f, 0.f);
    for (int p = s; p < e; ++p) {
        long n = g_csr_src[p];
        float4 v1 = *(const float4*)(s1 + n * sld + (t4 << 2));
        float4 v2 = *(const float4*)(s2 + n * sld + (t4 << 2));
        a1.x += v1.x; a1.y += v1.y; a1.z += v1.z; a1.w += v1.w;
        a2.x += v2.x; a2.y += v2.y; a2.z += v2.z; a2.w += v2.w;
    }
    a1.x *= scale; a1.y *= scale; a1.z *= scale; a1.w *= scale;
    a2.x *= scale; a2.y *= scale; a2.z *= scale; a2.w *= scale;
    *(float4*)(d1 + (long)j * Dd + (t4 << 2)) = a1;
    *(float4*)(d2 + (long)j * Dd + (t4 << 2)) = a2;
}

// ---------- FUSED hop-3 gather + attn scalar + split (float4, block 64) ----------
__global__ void gather_attnsplit(const float* __restrict__ vb, const float* __restrict__ kb,
                                 float scale) {
    int row = blockIdx.x, t4 = threadIdx.x;
    int s = g_rowstart[row], e = g_rowstart[row + 1];
    float4 av = make_float4(0.f, 0.f, 0.f, 0.f);
    float4 ak = make_float4(0.f, 0.f, 0.f, 0.f);
    for (int p = s; p < e; ++p) {
        long n = g_csr_src[p];
        float4 v = *(const float4*)(vb + n * Dd + (t4 << 2));
        float4 k = *(const float4*)(kb + n * Dd + (t4 << 2));
        av.x += v.x; av.y += v.y; av.z += v.z; av.w += v.w;
        ak.x += k.x; ak.y += k.y; ak.z += k.z; ak.w += k.w;
    }
    av.x *= scale; av.y *= scale; av.z *= scale; av.w *= scale;
    ak.x *= scale; ak.y *= scale; ak.z *= scale; ak.w *= scale;
    float4 q = *(const float4*)(&g_qkv[(size_t)row * QLD + (t4 << 2)]);
    float pr = q.x * ak.x + q.y * ak.y + q.z * ak.z + q.w * ak.w;
    pr = warp_sum(pr);
    __shared__ float sh[2];
    int w = t4 >> 5, l = t4 & 31;
    if (l == 0) sh[w] = pr;
    __syncthreads();
    float sdot = sh[0] + sh[1];
    float vv[4] = {av.x * sdot, av.y * sdot, av.z * sdot, av.w * sdot};
    size_t base = (size_t)row * Dd + (t4 << 2);
#pragma unroll
    for (int i = 0; i < 4; ++i) {
        __nv_bfloat16 hi, lo;
        split2(vv[i], hi, lo);
        g_a_hi[base + i] = hi;
        g_a_lo[base + i] = lo;
    }
}

// z from bf16-split q
__global__ void zcalc_kernel() {
    long gt = (long)blockIdx.x * 256 + threadIdx.x;
    int row = (int)(gt >> 5), lane = (int)(gt & 31);
    int b = row >> 13;
    float s = 0.f;
#pragma unroll
    for (int it = 0; it < 8; it++) {
        int d = it * 32 + lane;
        float q = __bfloat162float(g_a_hi[(size_t)row * Dd + d]) +
                  __bfloat162float(g_a_lo[(size_t)row * Dd + d]);
        s += q * g_ksum[b * Dd + d];
    }
    s = warp_sum(s);
    if (lane == 0) g_scal[row] = 1.0f / (s + 1e-6f);
}

__global__ void head_kernel(const float* __restrict__ w, const float* __restrict__ hb,
                            float* __restrict__ out) {
    long gt = (long)blockIdx.x * 256 + threadIdx.x;
    int row = (int)(gt >> 5), lane = (int)(gt & 31);
    float a0 = 0.f, a1 = 0.f, a2 = 0.f;
#pragma unroll
    for (int it = 0; it < 8; it++) {
        int d = it * 32 + lane;
        float hv = g_h[(size_t)row * Dd + d];
        a0 += hv * w[d * 3 + 0];
        a1 += hv * w[d * 3 + 1];
        a2 += hv * w[d * 3 + 2];
    }
    a0 = warp_sum(a0); a1 = warp_sum(a1); a2 = warp_sum(a2);
    if (lane == 0) {
        out[(size_t)row * 3 + 0] = a0 + hb[0];
        out[(size_t)row * 3 + 1] = a1 + hb[1];
        out[(size_t)row * 3 + 2] = a2 + hb[2];
    }
}

// ===================== host =====================
extern "C" void kernel_launch(void* const* d_in, const int* in_sizes, int n_in,
                              void* d_out, int out_size) {
    const float* x        = (const float*)d_in[0];
    const int*   knn      = (const int*)  d_in[1];
    const float* emb_w    = (const float*)d_in[2];
    const float* emb_b    = (const float*)d_in[3];
    const float* norm_g   = (const float*)d_in[4];
    const float* norm_b   = (const float*)d_in[5];
    const float* grf_qkv  = (const float*)d_in[6];
    const float* grf_outw = (const float*)d_in[7];
    const float* grf_outb = (const float*)d_in[8];
    const float* attn_qkv = (const float*)d_in[9];
    const float* attn_outw= (const float*)d_in[10];
    const float* attn_outb= (const float*)d_in[11];
    const float* head_w   = (const float*)d_in[12];
    const float* head_b   = (const float*)d_in[13];
    float* out = (float*)d_out;

    static int smem_set = 0;
    if (!smem_set) {
        cudaFuncSetAttribute(tc_gemm, cudaFuncAttributeMaxDynamicSharedMemorySize, SM_GEMM);
        smem_set = 1;
    }

    float *h, *qkv, *va, *vb, *ka, *kb, *scal, *kvm, *ksum;
    int *deg, *cursor;
    cudaGetSymbolAddress((void**)&h,    g_h);
    cudaGetSymbolAddress((void**)&qkv,  g_qkv);
    cudaGetSymbolAddress((void**)&va,   g_va);
    cudaGetSymbolAddress((void**)&vb,   g_vb);
    cudaGetSymbolAddress((void**)&ka,   g_ka);
    cudaGetSymbolAddress((void**)&kb,   g_kb);
    cudaGetSymbolAddress((void**)&scal, g_scal);
    cudaGetSymbolAddress((void**)&kvm,  g_kvm);
    cudaGetSymbolAddress((void**)&ksum, g_ksum);
    cudaGetSymbolAddress((void**)&deg,    g_deg);
    cudaGetSymbolAddress((void**)&cursor, g_cursor);
    __nv_bfloat16 *hnh, *hnl, *ah, *al, *vbh, *vbl, *kth, *ktl, *vth, *vtl, *kvth, *kvtl;
    __nv_bfloat16 *wgqh, *wgql, *waqh, *waql, *wgoh, *wgol, *waoh, *waol;
    cudaGetSymbolAddress((void**)&hnh, g_hn_hi); cudaGetSymbolAddress((void**)&hnl, g_hn_lo);
    cudaGetSymbolAddress((void**)&ah,  g_a_hi);  cudaGetSymbolAddress((void**)&al,  g_a_lo);
    cudaGetSymbolAddress((void**)&vbh, g_vbh);   cudaGetSymbolAddress((void**)&vbl, g_vbl);
    cudaGetSymbolAddress((void**)&kth, g_kT_hi); cudaGetSymbolAddress((void**)&ktl, g_kT_lo);
    cudaGetSymbolAddress((void**)&vth, g_vT_hi); cudaGetSymbolAddress((void**)&vtl, g_vT_lo);
    cudaGetSymbolAddress((void**)&kvth, g_kvT_hi); cudaGetSymbolAddress((void**)&kvtl, g_kvT_lo);
    cudaGetSymbolAddress((void**)&wgqh, g_wgq_hi); cudaGetSymbolAddress((void**)&wgql, g_wgq_lo);
    cudaGetSymbolAddress((void**)&waqh, g_waq_hi); cudaGetSymbolAddress((void**)&waql, g_waq_lo);
    cudaGetSymbolAddress((void**)&wgoh, g_wgo_hi); cudaGetSymbolAddress((void**)&wgol, g_wgo_lo);
    cudaGetSymbolAddress((void**)&waoh, g_wao_hi); cudaGetSymbolAddress((void**)&waol, g_wao_lo);

    const float s_hop = 1.0f / ((float)Kk + 1e-6f);
    const int egrid = BN * Kk / 256;

    // ---- front-loaded so tc_gemm is launch #4 (ncu capture target) ----
    tsplit<<<dim3(24, 8, Ll), 256>>>(grf_qkv, QLD, (long)Dd * QLD, wgqh, wgql, Dd, (long)QLD * Dd);
    embed_kernel<<<BN, Dd>>>(x, emb_w, emb_b);
    ln_kernel<<<BN, Dd>>>(norm_g, norm_b);
    tc_gemm<<<dim3(6, 512, 1), 256, SM_GEMM>>>(
        hnh, hnl, Dd, 0, wgqh, wgql, Dd, 0,
        1, 8, qkv, QLD, 0, nullptr, nullptr, nullptr, nullptr, 0, 0, 0, 1);

    // ---- CSR build (needed before first gather) ----
    zero_kernel<<<BN / 1024, 256>>>((float4*)deg, BN / 4);
    zero_kernel<<<BN / 1024, 256>>>((float4*)cursor, BN / 4);
    count_kernel<<<egrid, 256>>>(knn);
    scan1<<<64, 1024>>>();
    scan2<<<1, 1>>>();
    scan3<<<64, 1024>>>();
    fill_kernel<<<egrid, 256>>>(knn);

    // ---- remaining weight transpose + split ----
    tsplit<<<dim3(24, 8, Ll), 256>>>(attn_qkv, QLD, (long)Dd * QLD, waqh, waql, Dd, (long)QLD * Dd);
    tsplit<<<dim3(8, 8, Ll), 256>>>(grf_outw, Dd, (long)Dd * Dd, wgoh, wgol, Dd, (long)Dd * Dd);
    tsplit<<<dim3(8, 8, Ll), 256>>>(attn_outw, Dd, (long)Dd * Dd, waoh, waol, Dd, (long)Dd * Dd);

    for (int i = 0; i < Ll; i++) {
        // ===== GRF block =====
        if (i > 0) {
            ln_kernel<<<BN, Dd>>>(norm_g + (size_t)(2 * i) * Dd, norm_b + (size_t)(2 * i) * Dd);
            tc_gemm<<<dim3(6, 512, 1), 256, SM_GEMM>>>(
                hnh, hnl, Dd, 0, wgqh + (size_t)i * QLD * Dd, wgql + (size_t)i * QLD * Dd, Dd, 0,
                1, 8, qkv, QLD, 0, nullptr, nullptr, nullptr, nullptr, 0, 0, 0, 1);
        }
        gather2<<<BN / 2, 128>>>(qkv + 2 * Dd, qkv + Dd, QLD, s_hop, va, ka);
        gather2<<<BN / 2, 128>>>(va, ka, Dd, s_hop, vb, kb);
        gather_attnsplit<<<BN, 64>>>(vb, kb, s_hop);
        tc_gemm<<<dim3(2, 512, 1), 256, SM_GEMM>>>(
            ah, al, Dd, 0, wgoh + (size_t)i * Dd * Dd, wgol + (size_t)i * Dd * Dd, Dd, 0,
            1, 8, h, Dd, 0, grf_outb + (size_t)i * Dd, nullptr, nullptr, nullptr, 0, 0, 0, 2);

        // ===== linear attention block =====
        ln_kernel<<<BN, Dd>>>(norm_g + (size_t)(2 * i + 1) * Dd, norm_b + (size_t)(2 * i + 1) * Dd);
        tc_gemm<<<dim3(6, 512, 1), 256, SM_GEMM>>>(
            hnh, hnl, Dd, 0, waqh + (size_t)i * QLD * Dd, waql + (size_t)i * QLD * Dd, Dd, 0,
            1, 8, qkv, QLD, 0, nullptr, nullptr, ah, al, Dd, 2 * Dd, Dd, 16 | 8);
        // combined zero of kvm + ksum
        zero2_kernel<<<(Bc * Dd * Dd / 4 + Bc * Dd / 4 + 255) / 256, 256>>>(
            (float4*)kvm, (long)Bc * Dd * Dd / 4, (float4*)ksum, (long)Bc * Dd / 4);
        tsplit2_kv<<<dim3(8, 256, Bc), 256>>>(kth, ktl, vth, vtl);
        tc_gemm<<<dim3(2, 2, Bc * 16), 256, SM_GEMM>>>(
            kth, ktl, Nn, Dd, vth, vtl, Nn, Dd,
            16, 16, kvm, Dd, Dd, nullptr, nullptr, nullptr, nullptr, 0, 0, 0, 4);
        zcalc_kernel<<<BN * 32 / 256, 256>>>();
        tsplit<<<dim3(8, 8, Bc), 256>>>(kvm, Dd, (long)Dd * Dd, kvth, kvtl, Dd, (long)Dd * Dd);
        tc_gemm<<<dim3(2, 64, Bc), 256, SM_GEMM>>>(
            ah, al, Dd, Nn, kvth, kvtl, Dd, Dd,
            1, 8, nullptr, 0, Nn, nullptr, scal, vbh, vbl, Dd, 0, Dd, 8);
        tc_gemm<<<dim3(2, 512, 1), 256, SM_GEMM>>>(
            vbh, vbl, Dd, 0, waoh + (size_t)i * Dd * Dd, waol + (size_t)i * Dd * Dd, Dd, 0,
            1, 8, h, Dd, 0, attn_outb + (size_t)i * Dd, nullptr, nullptr, nullptr, 0, 0, 0, 2);
    }

    head_kernel<<<BN * 32 / 256, 256>>>(head_w, head_b, out);
}

// round 17
// speedup vs baseline: 1.3057x; 1.0634x over previous
#include <cuda_runtime.h>
#include <cuda_bf16.h>
#include <cstdint>

#define Bc 8
#define Nn 8192
#define Kk 6
#define Dd 256
#define Ll 5
#define BN 65536
#define QLD 768

// ===================== device scratch =====================
__device__ float g_h  [(size_t)BN * Dd];
__device__ float g_qkv[(size_t)BN * 3 * Dd];
__device__ float g_va [(size_t)BN * Dd];
__device__ float g_vb [(size_t)BN * Dd];
__device__ float g_ka [(size_t)BN * Dd];
__device__ float g_kb [(size_t)BN * Dd];
__device__ float g_scal[BN];
__device__ float g_kvm [Bc * Dd * Dd];
__device__ float g_ksum[Bc * Dd];

// CSR (transposed adjacency)
__device__ int g_deg[BN];
__device__ int g_cursor[BN];
__device__ int g_rowstart[BN + 1];
__device__ int g_csr_src[BN * Kk];
__device__ int g_part[64];
__device__ int g_partoff[64];

__device__ __align__(128) __nv_bfloat16 g_hn_hi[(size_t)BN * Dd], g_hn_lo[(size_t)BN * Dd];
__device__ __align__(128) __nv_bfloat16 g_a_hi [(size_t)BN * Dd], g_a_lo [(size_t)BN * Dd];
__device__ __align__(128) __nv_bfloat16 g_vbh  [(size_t)BN * Dd], g_vbl  [(size_t)BN * Dd];
__device__ __align__(128) __nv_bfloat16 g_kT_hi[(size_t)Bc * Dd * Nn], g_kT_lo[(size_t)Bc * Dd * Nn];
__device__ __align__(128) __nv_bfloat16 g_vT_hi[(size_t)Bc * Dd * Nn], g_vT_lo[(size_t)Bc * Dd * Nn];
__device__ __align__(128) __nv_bfloat16 g_kvT_hi[Bc * Dd * Dd], g_kvT_lo[Bc * Dd * Dd];
__device__ __align__(128) __nv_bfloat16 g_wgq_hi[Ll * 3 * Dd * Dd], g_wgq_lo[Ll * 3 * Dd * Dd];
__device__ __align__(128) __nv_bfloat16 g_waq_hi[Ll * 3 * Dd * Dd], g_waq_lo[Ll * 3 * Dd * Dd];
__device__ __align__(128) __nv_bfloat16 g_wgo_hi[Ll * Dd * Dd],     g_wgo_lo[Ll * Dd * Dd];
__device__ __align__(128) __nv_bfloat16 g_wao_hi[Ll * Dd * Dd],     g_wao_lo[Ll * Dd * Dd];

// ===================== PTX helpers (base PTX, sm_103-legal) ============
__device__ __forceinline__ uint32_t smem_to_u32(const void* p) {
    uint32_t a;
    asm("{ .reg .u64 t; cvta.to.shared.u64 t, %1; cvt.u32.u64 %0, t; }" : "=r"(a) : "l"(p));
    return a;
}
#define LDSM_X4(r0, r1, r2, r3, addr) \
    asm volatile("ldmatrix.sync.aligned.m8n8.x4.shared.b16 {%0,%1,%2,%3}, [%4];" \
        : "=r"(r0), "=r"(r1), "=r"(r2), "=r"(r3) : "r"(addr))
#define MMA_BF16(d, a, b) \
    asm volatile("mma.sync.aligned.m16n8k16.row.col.f32.bf16.bf16.f32 " \
        "{%0,%1,%2,%3}, {%4,%5,%6,%7}, {%8,%9}, {%0,%1,%2,%3};" \
        : "+f"((d)[0]), "+f"((d)[1]), "+f"((d)[2]), "+f"((d)[3]) \
        : "r"((a)[0]), "r"((a)[1]), "r"((a)[2]), "r"((a)[3]), "r"((b)[0]), "r"((b)[1]))
#define CP_ASYNC16(s, g) \
    asm volatile("cp.async.cg.shared.global [%0], [%1], 16;" :: "r"(s), "l"(g))
#define CP_COMMIT() asm volatile("cp.async.commit_group;" ::: "memory")
#define CP_WAIT0()  asm volatile("cp.async.wait_group 0;" ::: "memory")

__device__ __forceinline__ void split2(float v, __nv_bfloat16& hi, __nv_bfloat16& lo) {
    hi = __float2bfloat16(v);
    lo = __float2bfloat16(v - __bfloat162float(hi));
}

// ===================== tensor-core GEMM (FROZEN) ==============
#define STG 40960
#define SM_GEMM 81920

__global__ __launch_bounds__(256, 2) void tc_gemm(
    const __nv_bfloat16* __restrict__ Ah, const __nv_bfloat16* __restrict__ Al, int lda, int aBatchRows,
    const __nv_bfloat16* __restrict__ Bh, const __nv_bfloat16* __restrict__ Bl, int ldb, int bBatchRows,
    int nsplit, int kChunks,
    float* __restrict__ C, int ldc, int cBatchRows,
    const float* __restrict__ bias, const float* __restrict__ rowscale,
    __nv_bfloat16* __restrict__ Oh, __nv_bfloat16* __restrict__ Ol, int ldo,
    int reluLimit, int bf16Limit, int flags)
{
    extern __shared__ char dsm[];
    uint32_t sb = smem_to_u32(dsm);
    int t = threadIdx.x, wid = t >> 5, lane = t & 31;
    int batch = blockIdx.z / nsplit, ks = blockIdx.z % nsplit;
    int m0 = blockIdx.y * 128, n0 = blockIdx.x * 128;
    int kBase = ks * kChunks * 32;
    long aRow0 = (long)batch * aBatchRows + m0;
    long bRow0 = (long)batch * bBatchRows + n0;
    int wm = (wid & 1) * 64;
    int wn = (wid >> 1) * 32;

    float acc[4][4][4];
#pragma unroll
    for (int i = 0; i < 4; i++)
#pragma unroll
        for (int j = 0; j < 4; j++)
#pragma unroll
            for (int r = 0; r < 4; r++) acc[i][j][r] = 0.f;

    int lr = t >> 2, seg = t & 3;

#define LOAD_STAGE(c, st) do { \
        int kb = kBase + (c) * 32; \
        uint32_t sbase = sb + (st) * STG; \
        _Pragma("unroll") \
        for (int rr = 0; rr < 2; ++rr) { \
            int row = lr + rr * 64; \
            long ao = (aRow0 + row) * (long)lda + kb + seg * 8; \
            long bo = (bRow0 + row) * (long)ldb + kb + seg * 8; \
            uint32_t so = (uint32_t)row * 80 + seg * 16; \
            CP_ASYNC16(sbase + so,         (const char*)(Ah + ao)); \
            CP_ASYNC16(sbase + 10240 + so, (const char*)(Al + ao)); \
            CP_ASYNC16(sbase + 20480 + so, (const char*)(Bh + bo)); \
            CP_ASYNC16(sbase + 30720 + so, (const char*)(Bl + bo)); \
        } \
        CP_COMMIT(); \
    } while (0)

    LOAD_STAGE(0, 0);

    for (int c = 0; c < kChunks; ++c) {
        int st = c & 1;
        CP_WAIT0();
        __syncthreads();
        if (c + 1 < kChunks) LOAD_STAGE(c + 1, (c + 1) & 1);

        uint32_t uAh = sb + st * STG, uAl = uAh + 10240;
        uint32_t uBh = uAh + 20480,   uBl = uAh + 30720;
#pragma unroll
        for (int kk = 0; kk < 2; ++kk) {
            int kbb = kk * 16;
            uint32_t ah[4][4], al[4][4], bh[4][2], bl[4][2];
            int arow = (lane & 7) + ((lane >> 3) & 1) * 8;
            int acol = kbb + (lane >> 4) * 8;
#pragma unroll
            for (int mt = 0; mt < 4; ++mt) {
                uint32_t off = (uint32_t)(wm + mt * 16 + arow) * 80 + acol * 2;
                LDSM_X4(ah[mt][0], ah[mt][1], ah[mt][2], ah[mt][3], uAh + off);
                LDSM_X4(al[mt][0], al[mt][1], al[mt][2], al[mt][3], uAl + off);
            }
            int brow = (lane & 7) + ((lane >> 4) & 1) * 8;
            int bcol = kbb + ((lane >> 3) & 1) * 8;
#pragma unroll
            for (int p = 0; p < 2; ++p) {
                uint32_t off = (uint32_t)(wn + p * 16 + brow) * 80 + bcol * 2;
                LDSM_X4(bh[2 * p][0], bh[2 * p][1], bh[2 * p + 1][0], bh[2 * p + 1][1], uBh + off);
                LDSM_X4(bl[2 * p][0], bl[2 * p][1], bl[2 * p + 1][0], bl[2 * p + 1][1], uBl + off);
            }
#pragma unroll
            for (int mt = 0; mt < 4; ++mt)
#pragma unroll
                for (int nt = 0; nt < 4; ++nt) {
                    MMA_BF16(acc[mt][nt], ah[mt], bh[nt]);
                    MMA_BF16(acc[mt][nt], ah[mt], bl[nt]);
                    MMA_BF16(acc[mt][nt], al[mt], bh[nt]);
                }
        }
    }

    // epilogue
#pragma unroll
    for (int mt = 0; mt < 4; ++mt) {
        int r0g = m0 + wm + mt * 16 + (lane >> 2);
        long row0 = (long)batch * cBatchRows + r0g;
        long row1 = row0 + 8;
        float rs0 = rowscale ? rowscale[row0] : 1.f;
        float rs1 = rowscale ? rowscale[row1] : 1.f;
#pragma unroll
        for (int nt = 0; nt < 4; ++nt) {
            int c0 = n0 + wn + nt * 8 + (lane & 3) * 2;
#pragma unroll
            for (int half = 0; half < 2; ++half) {
                long row = half ? row1 : row0;
                float rs = half ? rs1 : rs0;
#pragma unroll
                for (int cc = 0; cc < 2; ++cc) {
                    float v = acc[mt][nt][half * 2 + cc] * rs;
                    int n = c0 + cc;
                    if (n < reluLimit) v = fmaxf(v, 0.f) + 1e-6f;
                    if (bias) v += bias[n];
                    if (flags & 1) C[row * ldc + n] = v;
                    if (flags & 2) C[row * ldc + n] += v;
                    if (flags & 4) atomicAdd(&C[row * ldc + n], v);
                    if ((flags & 16) && n >= bf16Limit) C[row * ldc + n] = v;
                    if ((flags & 8) && n < bf16Limit) {
                        __nv_bfloat16 hi, lo;
                        split2(v, hi, lo);
                        Oh[row * ldo + n] = hi;
                        Ol[row * ldo + n] = lo;
                    }
                }
            }
        }
    }
}

// ===================== SIMT kernels =====================
__device__ __forceinline__ float warp_sum(float v) {
#pragma unroll
    for (int o = 16; o > 0; o >>= 1) v += __shfl_xor_sync(0xffffffffu, v, o);
    return v;
}

__global__ void embed_kernel(const float* __restrict__ x, const float* __restrict__ w,
                             const float* __restrict__ b) {
    int row = blockIdx.x, t = threadIdx.x;
    float x0 = x[row * 3], x1 = x[row * 3 + 1], x2 = x[row * 3 + 2];
    g_h[(size_t)row * Dd + t] = b[t] + x0 * w[t] + x1 * w[Dd + t] + x2 * w[2 * Dd + t];
}

// LN: 4 rows per 256-thread block, float4 I/O, 2-warp row reduction.
__global__ void ln_kernel(const float* __restrict__ g, const float* __restrict__ b) {
    int rl = threadIdx.x >> 6;             // row within block 0..3
    int t64 = threadIdx.x & 63;            // float4 lane within row
    long row = (long)blockIdx.x * 4 + rl;
    float4 x = *(const float4*)(g_h + row * Dd + (t64 << 2));
    float s  = x.x + x.y + x.z + x.w;
    float s2 = x.x * x.x + x.y * x.y + x.z * x.z + x.w * x.w;
    s = warp_sum(s);
    s2 = warp_sum(s2);
    __shared__ float sh1[8], sh2[8];
    int w = threadIdx.x >> 5;
    if ((threadIdx.x & 31) == 0) { sh1[w] = s; sh2[w] = s2; }
    __syncthreads();
    float tot  = sh1[rl * 2] + sh1[rl * 2 + 1];
    float tot2 = sh2[rl * 2] + sh2[rl * 2 + 1];
    float m = tot * (1.0f / Dd);
    float var = fmaxf(tot2 * (1.0f / Dd) - m * m, 0.0f);
    float inv = rsqrtf(var + 1e-5f);
    float4 gg = *(const float4*)(g + (t64 << 2));
    float4 bb = *(const float4*)(b + (t64 << 2));
    float y0 = (x.x - m) * inv * gg.x + bb.x;
    float y1 = (x.y - m) * inv * gg.y + bb.y;
    float y2 = (x.z - m) * inv * gg.z + bb.z;
    float y3 = (x.w - m) * inv * gg.w + bb.w;
    __nv_bfloat16 h0, h1, h2, h3, l0, l1, l2, l3;
    split2(y0, h0, l0); split2(y1, h1, l1); split2(y2, h2, l2); split2(y3, h3, l3);
    __nv_bfloat162 hp0 = {h0, h1}, hp1 = {h2, h3}, lp0 = {l0, l1}, lp1 = {l2, l3};
    uint2 hv = {*(uint32_t*)&hp0, *(uint32_t*)&hp1};
    uint2 lv = {*(uint32_t*)&lp0, *(uint32_t*)&lp1};
    *(uint2*)(g_hn_hi + row * Dd + (t64 << 2)) = hv;
    *(uint2*)(g_hn_lo + row * Dd + (t64 << 2)) = lv;
}

__global__ void tsplit(const float* __restrict__ in, int ldi, long inB,
                       __nv_bfloat16* __restrict__ oh, __nv_bfloat16* __restrict__ ol,
                       int ldo, long oB) {
    int z = blockIdx.z;
    in += (long)z * inB; oh += (long)z * oB; ol += (long)z * oB;
    __shared__ float tb[32][33];
    int c0 = blockIdx.x * 32, r0 = blockIdx.y * 32;
    int tx = threadIdx.x & 31, ty = threadIdx.x >> 5;
#pragma unroll
    for (int i = 0; i < 4; ++i) {
        int r = ty + i * 8;
        tb[r][tx] = in[(long)(r0 + r) * ldi + c0 + tx];
    }
    __syncthreads();
#pragma unroll
    for (int i = 0; i < 4; ++i) {
        int c = ty + i * 8;
        float v = tb[tx][c];
        __nv_bfloat16 hi, lo;
        split2(v, hi, lo);
        oh[(long)(c0 + c) * ldo + r0 + tx] = hi;
        ol[(long)(c0 + c) * ldo + r0 + tx] = lo;
    }
}

// FUSED: transpose+split k AND v from qkv, plus ksum partial reduction of k.
__global__ void tsplit2_kv(__nv_bfloat16* __restrict__ kth, __nv_bfloat16* __restrict__ ktl,
                           __nv_bfloat16* __restrict__ vth, __nv_bfloat16* __restrict__ vtl) {
    int z = blockIdx.z;
    int c0 = blockIdx.x * 32, r0 = blockIdx.y * 32;
    const float* base = g_qkv + ((size_t)z * Nn + r0) * QLD;
    __shared__ float tk[32][33], tv[32][33];
    __shared__ float csum[32];
    int tx = threadIdx.x & 31, ty = threadIdx.x >> 5;
    if (threadIdx.x < 32) csum[threadIdx.x] = 0.f;
    float part = 0.f;
#pragma unroll
    for (int i = 0; i < 4; ++i) {
        int r = ty + i * 8;
        float kv_ = base[(size_t)r * QLD + Dd + c0 + tx];
        tk[r][tx] = kv_;
        part += kv_;
        tv[r][tx] = base[(size_t)r * QLD + 2 * Dd + c0 + tx];
    }
    __syncthreads();
    atomicAdd(&csum[tx], part);
    size_t ob = ((size_t)z * Dd) * Nn;
#pragma unroll
    for (int i = 0; i < 4; ++i) {
        int c = ty + i * 8;
        __nv_bfloat16 hi, lo;
        split2(tk[tx][c], hi, lo);
        kth[ob + (size_t)(c0 + c) * Nn + r0 + tx] = hi;
        ktl[ob + (size_t)(c0 + c) * Nn + r0 + tx] = lo;
        split2(tv[tx][c], hi, lo);
        vth[ob + (size_t)(c0 + c) * Nn + r0 + tx] = hi;
        vtl[ob + (size_t)(c0 + c) * Nn + r0 + tx] = lo;
    }
    __syncthreads();
    if (threadIdx.x < 32)
        atomicAdd(&g_ksum[z * Dd + c0 + threadIdx.x], csum[threadIdx.x]);
}

__global__ void zero_kernel(float4* __restrict__ p, long n4) {
    long i = (long)blockIdx.x * 256 + threadIdx.x;
    if (i < n4) p[i] = make_float4(0.f, 0.f, 0.f, 0.f);
}

__global__ void zero2_kernel(float4* __restrict__ a, long n4a,
                             float4* __restrict__ b, long n4b) {
    long i = (long)blockIdx.x * 256 + threadIdx.x;
    if (i < n4a) a[i] = make_float4(0.f, 0.f, 0.f, 0.f);
    else if (i < n4a + n4b) b[i - n4a] = make_float4(0.f, 0.f, 0.f, 0.f);
}

// ---------- CSR build ----------
__global__ void count_kernel(const int* __restrict__ knn) {
    int e = blockIdx.x * 256 + threadIdx.x;
    int srow = e / Kk;
    int b = srow >> 13;
    atomicAdd(&g_deg[(b << 13) + knn[e]], 1);
}

__global__ void scan1() {
    int b = blockIdx.x, t = threadIdx.x;
    int v = g_deg[b * 1024 + t];
    v = (int)warp_sum((float)v);
    __shared__ int sh[32];
    if ((t & 31) == 0) sh[t >> 5] = v;
    __syncthreads();
    if (t == 0) {
        int s = 0;
#pragma unroll
        for (int i = 0; i < 32; i++) s += sh[i];
        g_part[b] = s;
    }
}
__global__ void scan2() {
    int run = 0;
    for (int i = 0; i < 64; i++) { g_partoff[i] = run; run += g_part[i]; }
}
__global__ void scan3() {
    __shared__ int sh[1024];
    int b = blockIdx.x, t = threadIdx.x;
    int v = g_deg[b * 1024 + t];
    sh[t] = v;
    __syncthreads();
#pragma unroll
    for (int off = 1; off < 1024; off <<= 1) {
        int x = (t >= off) ? sh[t - off] : 0;
        __syncthreads();
        sh[t] += x;
        __syncthreads();
    }
    int incl = sh[t];
    g_rowstart[b * 1024 + t] = g_partoff[b] + incl - v;
    if (b == 63 && t == 1023) g_rowstart[BN] = g_partoff[b] + incl;
}

__global__ void fill_kernel(const int* __restrict__ knn) {
    int e = blockIdx.x * 256 + threadIdx.x;
    int srow = e / Kk;
    int b = srow >> 13;
    int dst = (b << 13) + knn[e];
    int pos = g_rowstart[dst] + atomicAdd(&g_cursor[dst], 1);
    g_csr_src[pos] = srow;
}

// ---------- fused k/v gather hop: float4, 128-thread blocks ----------
__global__ void gather2(const float* __restrict__ s1, const float* __restrict__ s2, int sld,
                        float scale, float* __restrict__ d1, float* __restrict__ d2) {
    int w = threadIdx.x >> 5;
    int j = blockIdx.x * 2 + (w >> 1);
    int t4 = ((w & 1) << 5) + (threadIdx.x & 31);
    int s = g_rowstart[j], e = g_rowstart[j + 1];
    float4 a1 = make_float4(0.f, 0.f, 0.f, 0.f);
    float4 a2 = make_float4(0.f, 0.f, 0.f, 0.f);
    for (int p = s; p < e; ++p) {
        long n = g_csr_src[p];
        float4 v1 = *(const float4*)(s1 + n * sld + (t4 << 2));
        float4 v2 = *(const float4*)(s2 + n * sld + (t4 << 2));
        a1.x += v1.x; a1.y += v1.y; a1.z += v1.z; a1.w += v1.w;
        a2.x += v2.x; a2.y += v2.y; a2.z += v2.z; a2.w += v2.w;
    }
    a1.x *= scale; a1.y *= scale; a1.z *= scale; a1.w *= scale;
    a2.x *= scale; a2.y *= scale; a2.z *= scale; a2.w *= scale;
    *(float4*)(d1 + (long)j * Dd + (t4 << 2)) = a1;
    *(float4*)(d2 + (long)j * Dd + (t4 << 2)) = a2;
}

// ---------- FUSED hop-3 gather + attn scalar + split (float4, block 64) ----------
__global__ void gather_attnsplit(const float* __restrict__ vb, const float* __restrict__ kb,
                                 float scale) {
    int row = blockIdx.x, t4 = threadIdx.x;
    int s = g_rowstart[row], e = g_rowstart[row + 1];
    float4 av = make_float4(0.f, 0.f, 0.f, 0.f);
    float4 ak = make_float4(0.f, 0.f, 0.f, 0.f);
    for (int p = s; p < e; ++p) {
        long n = g_csr_src[p];
        float4 v = *(const float4*)(vb + n * Dd + (t4 << 2));
        float4 k = *(const float4*)(kb + n * Dd + (t4 << 2));
        av.x += v.x; av.y += v.y; av.z += v.z; av.w += v.w;
        ak.x += k.x; ak.y += k.y; ak.z += k.z; ak.w += k.w;
    }
    av.x *= scale; av.y *= scale; av.z *= scale; av.w *= scale;
    ak.x *= scale; ak.y *= scale; ak.z *= scale; ak.w *= scale;
    float4 q = *(const float4*)(&g_qkv[(size_t)row * QLD + (t4 << 2)]);
    float pr = q.x * ak.x + q.y * ak.y + q.z * ak.z + q.w * ak.w;
    pr = warp_sum(pr);
    __shared__ float sh[2];
    int w = t4 >> 5, l = t4 & 31;
    if (l == 0) sh[w] = pr;
    __syncthreads();
    float sdot = sh[0] + sh[1];
    float vv[4] = {av.x * sdot, av.y * sdot, av.z * sdot, av.w * sdot};
    size_t base = (size_t)row * Dd + (t4 << 2);
#pragma unroll
    for (int i = 0; i < 4; ++i) {
        __nv_bfloat16 hi, lo;
        split2(vv[i], hi, lo);
        g_a_hi[base + i] = hi;
        g_a_lo[base + i] = lo;
    }
}

// z from bf16-split q
__global__ void zcalc_kernel() {
    long gt = (long)blockIdx.x * 256 + threadIdx.x;
    int row = (int)(gt >> 5), lane = (int)(gt & 31);
    int b = row >> 13;
    float s = 0.f;
#pragma unroll
    for (int it = 0; it < 8; it++) {
        int d = it * 32 + lane;
        float q = __bfloat162float(g_a_hi[(size_t)row * Dd + d]) +
                  __bfloat162float(g_a_lo[(size_t)row * Dd + d]);
        s += q * g_ksum[b * Dd + d];
    }
    s = warp_sum(s);
    if (lane == 0) g_scal[row] = 1.0f / (s + 1e-6f);
}

__global__ void head_kernel(const float* __restrict__ w, const float* __restrict__ hb,
                            float* __restrict__ out) {
    long gt = (long)blockIdx.x * 256 + threadIdx.x;
    int row = (int)(gt >> 5), lane = (int)(gt & 31);
    float a0 = 0.f, a1 = 0.f, a2 = 0.f;
#pragma unroll
    for (int it = 0; it < 8; it++) {
        int d = it * 32 + lane;
        float hv = g_h[(size_t)row * Dd + d];
        a0 += hv * w[d * 3 + 0];
        a1 += hv * w[d * 3 + 1];
        a2 += hv * w[d * 3 + 2];
    }
    a0 = warp_sum(a0); a1 = warp_sum(a1); a2 = warp_sum(a2);
    if (lane == 0) {
        out[(size_t)row * 3 + 0] = a0 + hb[0];
        out[(size_t)row * 3 + 1] = a1 + hb[1];
        out[(size_t)row * 3 + 2] = a2 + hb[2];
    }
}

// ===================== host =====================
extern "C" void kernel_launch(void* const* d_in, const int* in_sizes, int n_in,
                              void* d_out, int out_size) {
    const float* x        = (const float*)d_in[0];
    const int*   knn      = (const int*)  d_in[1];
    const float* emb_w    = (const float*)d_in[2];
    const float* emb_b    = (const float*)d_in[3];
    const float* norm_g   = (const float*)d_in[4];
    const float* norm_b   = (const float*)d_in[5];
    const float* grf_qkv  = (const float*)d_in[6];
    const float* grf_outw = (const float*)d_in[7];
    const float* grf_outb = (const float*)d_in[8];
    const float* attn_qkv = (const float*)d_in[9];
    const float* attn_outw= (const float*)d_in[10];
    const float* attn_outb= (const float*)d_in[11];
    const float* head_w   = (const float*)d_in[12];
    const float* head_b   = (const float*)d_in[13];
    float* out = (float*)d_out;

    static int smem_set = 0;
    if (!smem_set) {
        cudaFuncSetAttribute(tc_gemm, cudaFuncAttributeMaxDynamicSharedMemorySize, SM_GEMM);
        smem_set = 1;
    }

    float *h, *qkv, *va, *vb, *ka, *kb, *scal, *kvm, *ksum;
    int *deg, *cursor;
    cudaGetSymbolAddress((void**)&h,    g_h);
    cudaGetSymbolAddress((void**)&qkv,  g_qkv);
    cudaGetSymbolAddress((void**)&va,   g_va);
    cudaGetSymbolAddress((void**)&vb,   g_vb);
    cudaGetSymbolAddress((void**)&ka,   g_ka);
    cudaGetSymbolAddress((void**)&kb,   g_kb);
    cudaGetSymbolAddress((void**)&scal, g_scal);
    cudaGetSymbolAddress((void**)&kvm,  g_kvm);
    cudaGetSymbolAddress((void**)&ksum, g_ksum);
    cudaGetSymbolAddress((void**)&deg,    g_deg);
    cudaGetSymbolAddress((void**)&cursor, g_cursor);
    __nv_bfloat16 *hnh, *hnl, *ah, *al, *vbh, *vbl, *kth, *ktl, *vth, *vtl, *kvth, *kvtl;
    __nv_bfloat16 *wgqh, *wgql, *waqh, *waql, *wgoh, *wgol, *waoh, *waol;
    cudaGetSymbolAddress((void**)&hnh, g_hn_hi); cudaGetSymbolAddress((void**)&hnl, g_hn_lo);
    cudaGetSymbolAddress((void**)&ah,  g_a_hi);  cudaGetSymbolAddress((void**)&al,  g_a_lo);
    cudaGetSymbolAddress((void**)&vbh, g_vbh);   cudaGetSymbolAddress((void**)&vbl, g_vbl);
    cudaGetSymbolAddress((void**)&kth, g_kT_hi); cudaGetSymbolAddress((void**)&ktl, g_kT_lo);
    cudaGetSymbolAddress((void**)&vth, g_vT_hi); cudaGetSymbolAddress((void**)&vtl, g_vT_lo);
    cudaGetSymbolAddress((void**)&kvth, g_kvT_hi); cudaGetSymbolAddress((void**)&kvtl, g_kvT_lo);
    cudaGetSymbolAddress((void**)&wgqh, g_wgq_hi); cudaGetSymbolAddress((void**)&wgql, g_wgq_lo);
    cudaGetSymbolAddress((void**)&waqh, g_waq_hi); cudaGetSymbolAddress((void**)&waql, g_waq_lo);
    cudaGetSymbolAddress((void**)&wgoh, g_wgo_hi); cudaGetSymbolAddress((void**)&wgol, g_wgo_lo);
    cudaGetSymbolAddress((void**)&waoh, g_wao_hi); cudaGetSymbolAddress((void**)&waol, g_wao_lo);

    const float s_hop = 1.0f / ((float)Kk + 1e-6f);
    const int egrid = BN * Kk / 256;

    // ---- front-loaded so tc_gemm is launch #4 (ncu capture target) ----
    tsplit<<<dim3(24, 8, Ll), 256>>>(grf_qkv, QLD, (long)Dd * QLD, wgqh, wgql, Dd, (long)QLD * Dd);
    embed_kernel<<<BN, Dd>>>(x, emb_w, emb_b);
    ln_kernel<<<BN / 4, 256>>>(norm_g, norm_b);
    tc_gemm<<<dim3(6, 512, 1), 256, SM_GEMM>>>(
        hnh, hnl, Dd, 0, wgqh, wgql, Dd, 0,
        1, 8, qkv, QLD, 0, nullptr, nullptr, nullptr, nullptr, 0, 0, 0, 1);

    // ---- CSR build ----
    zero_kernel<<<BN / 1024, 256>>>((float4*)deg, BN / 4);
    zero_kernel<<<BN / 1024, 256>>>((float4*)cursor, BN / 4);
    count_kernel<<<egrid, 256>>>(knn);
    scan1<<<64, 1024>>>();
    scan2<<<1, 1>>>();
    scan3<<<64, 1024>>>();
    fill_kernel<<<egrid, 256>>>(knn);

    // ---- remaining weight transpose + split ----
    tsplit<<<dim3(24, 8, Ll), 256>>>(attn_qkv, QLD, (long)Dd * QLD, waqh, waql, Dd, (long)QLD * Dd);
    tsplit<<<dim3(8, 8, Ll), 256>>>(grf_outw, Dd, (long)Dd * Dd, wgoh, wgol, Dd, (long)Dd * Dd);
    tsplit<<<dim3(8, 8, Ll), 256>>>(attn_outw, Dd, (long)Dd * Dd, waoh, waol, Dd, (long)Dd * Dd);

    for (int i = 0; i < Ll; i++) {
        // ===== GRF block =====
        if (i > 0) {
            ln_kernel<<<BN / 4, 256>>>(norm_g + (size_t)(2 * i) * Dd, norm_b + (size_t)(2 * i) * Dd);
            tc_gemm<<<dim3(6, 512, 1), 256, SM_GEMM>>>(
                hnh, hnl, Dd, 0, wgqh + (size_t)i * QLD * Dd, wgql + (size_t)i * QLD * Dd, Dd, 0,
                1, 8, qkv, QLD, 0, nullptr, nullptr, nullptr, nullptr, 0, 0, 0, 1);
        }
        gather2<<<BN / 2, 128>>>(qkv + 2 * Dd, qkv + Dd, QLD, s_hop, va, ka);
        gather2<<<BN / 2, 128>>>(va, ka, Dd, s_hop, vb, kb);
        gather_attnsplit<<<BN, 64>>>(vb, kb, s_hop);
        tc_gemm<<<dim3(2, 512, 1), 256, SM_GEMM>>>(
            ah, al, Dd, 0, wgoh + (size_t)i * Dd * Dd, wgol + (size_t)i * Dd * Dd, Dd, 0,
            1, 8, h, Dd, 0, grf_outb + (size_t)i * Dd, nullptr, nullptr, nullptr, 0, 0, 0, 2);

        // ===== linear attention block =====
        ln_kernel<<<BN / 4, 256>>>(norm_g + (size_t)(2 * i + 1) * Dd, norm_b + (size_t)(2 * i + 1) * Dd);
        tc_gemm<<<dim3(6, 512, 1), 256, SM_GEMM>>>(
            hnh, hnl, Dd, 0, waqh + (size_t)i * QLD * Dd, waql + (size_t)i * QLD * Dd, Dd, 0,
            1, 8, qkv, QLD, 0, nullptr, nullptr, ah, al, Dd, 2 * Dd, Dd, 16 | 8);
        zero2_kernel<<<(Bc * Dd * Dd / 4 + Bc * Dd / 4 + 255) / 256, 256>>>(
            (float4*)kvm, (long)Bc * Dd * Dd / 4, (float4*)ksum, (long)Bc * Dd / 4);
        tsplit2_kv<<<dim3(8, 256, Bc), 256>>>(kth, ktl, vth, vtl);
        tc_gemm<<<dim3(2, 2, Bc * 16), 256, SM_GEMM>>>(
            kth, ktl, Nn, Dd, vth, vtl, Nn, Dd,
            16, 16, kvm, Dd, Dd, nullptr, nullptr, nullptr, nullptr, 0, 0, 0, 4);
        zcalc_kernel<<<BN * 32 / 256, 256>>>();
        tsplit<<<dim3(8, 8, Bc), 256>>>(kvm, Dd, (long)Dd * Dd, kvth, kvtl, Dd, (long)Dd * Dd);
        tc_gemm<<<dim3(2, 64, Bc), 256, SM_GEMM>>>(
            ah, al, Dd, Nn, kvth, kvtl, Dd, Dd,
            1, 8, nullptr, 0, Nn, nullptr, scal, vbh, vbl, Dd, 0, Dd, 8);
        tc_gemm<<<dim3(2, 512, 1), 256, SM_GEMM>>>(
            vbh, vbl, Dd, 0, waoh + (size_t)i * Dd * Dd, waol + (size_t)i * Dd * Dd, Dd, 0,
            1, 8, h, Dd, 0, attn_outb + (size_t)i * Dd, nullptr, nullptr, nullptr, 0, 0, 0, 2);
    }

    head_kernel<<<BN * 32 / 256, 256>>>(head_w, head_b, out);
}